// round 1
// baseline (speedup 1.0000x reference)
#include <cuda_runtime.h>
#include <cuda_bf16.h>
#include <math.h>

#define NROW 12288
#define DIM  512
#define FEAT 128
#define NBLK 48           // NROW / 256

// ---------------- scratch (device globals; no allocations allowed) ----------
__device__ float g_scale[FEAT];
__device__ float g_z[NROW * FEAT];
__device__ float g_s[NROW];
__device__ float g_d[NROW];
__device__ unsigned long long g_dkey[NROW];
__device__ int   g_rank[NROW];
__device__ float g_sortedD[NROW];
__device__ float g_expD[NROW];
__device__ float g_zs[NROW * FEAT];
__device__ float g_S0[(NROW + 1) * FEAT];     // exclusive prefix of zs (zero side)
__device__ float g_SufE[(NROW + 1) * FEAT];   // suffix of expD*zs (active side)
__device__ float g_c1suf[NROW + 1];           // suffix of expD
__device__ float g_T0[NBLK * FEAT];
__device__ float g_TS[NBLK * FEAT];
__device__ float g_Tc[NBLK];
__device__ float g_off0[NBLK * FEAT];
__device__ float g_offS[NBLK * FEAT];
__device__ float g_offc[NBLK];
__device__ int   g_k[NROW];

// ---------------- helpers ----------------------------------------------------
__device__ __forceinline__ unsigned int float_key(float x) {
    unsigned int u = __float_as_uint(x);
    return (u & 0x80000000u) ? ~u : (u | 0x80000000u);   // monotone float->uint
}

// ---------------- 1) per-feature scale = g[f] / ||v_f|| ----------------------
__global__ void scale_kernel(const float* __restrict__ v, const float* __restrict__ g) {
    int f = blockIdx.x;
    int t = threadIdx.x;          // 128 threads
    float ss = 0.f;
    for (int q = t; q < DIM; q += 128) {
        float vv = v[(size_t)f * DIM + q];
        ss += vv * vv;
    }
    __shared__ float red[4];
    for (int off = 16; off; off >>= 1) ss += __shfl_xor_sync(0xffffffffu, ss, off);
    if ((t & 31) == 0) red[t >> 5] = ss;
    __syncthreads();
    if (t == 0) {
        float tot = red[0] + red[1] + red[2] + red[3];
        g_scale[f] = g[f] / sqrtf(tot);
    }
}

// ---------------- 2) z = (x @ v.T) * scale + b  (fp32 SIMT tiled GEMM) -------
// BM=64, BN=128(all F), BK=32, 256 threads, thread tile 8x4.
__global__ void __launch_bounds__(256) gemm_z_kernel(const float* __restrict__ x,
                                                     const float* __restrict__ v,
                                                     const float* __restrict__ b) {
    __shared__ float xs[32][64];    // [kk][m]
    __shared__ float vs[32][128];   // [kk][f]
    const int bm  = blockIdx.x * 64;
    const int tid = threadIdx.x;
    const int tm0 = (tid >> 5) * 8;
    const int tn0 = (tid & 31) * 4;

    float acc[8][4];
#pragma unroll
    for (int i = 0; i < 8; i++)
#pragma unroll
        for (int j = 0; j < 4; j++) acc[i][j] = 0.f;

    for (int k0 = 0; k0 < DIM; k0 += 32) {
        // load x tile: 64x32 = 512 float4
#pragma unroll
        for (int l = 0; l < 2; l++) {
            int li = tid + l * 256;
            int r  = li >> 3;
            int c4 = li & 7;
            float4 xv = *(const float4*)(x + (size_t)(bm + r) * DIM + k0 + c4 * 4);
            xs[c4 * 4 + 0][r] = xv.x;
            xs[c4 * 4 + 1][r] = xv.y;
            xs[c4 * 4 + 2][r] = xv.z;
            xs[c4 * 4 + 3][r] = xv.w;
        }
        // load v tile: 128x32 = 1024 float4
#pragma unroll
        for (int l = 0; l < 4; l++) {
            int li = tid + l * 256;
            int f  = li >> 3;
            int c4 = li & 7;
            float4 vv = *(const float4*)(v + (size_t)f * DIM + k0 + c4 * 4);
            vs[c4 * 4 + 0][f] = vv.x;
            vs[c4 * 4 + 1][f] = vv.y;
            vs[c4 * 4 + 2][f] = vv.z;
            vs[c4 * 4 + 3][f] = vv.w;
        }
        __syncthreads();
#pragma unroll
        for (int kk = 0; kk < 32; kk++) {
            float4 a0 = *(const float4*)&xs[kk][tm0];
            float4 a1 = *(const float4*)&xs[kk][tm0 + 4];
            float4 bn = *(const float4*)&vs[kk][tn0];
            float rm[8] = {a0.x, a0.y, a0.z, a0.w, a1.x, a1.y, a1.z, a1.w};
            float rn[4] = {bn.x, bn.y, bn.z, bn.w};
#pragma unroll
            for (int i = 0; i < 8; i++)
#pragma unroll
                for (int j = 0; j < 4; j++) acc[i][j] += rm[i] * rn[j];
        }
        __syncthreads();
    }

    float scl[4], bb[4];
#pragma unroll
    for (int j = 0; j < 4; j++) {
        scl[j] = g_scale[tn0 + j];
        bb[j]  = b[tn0 + j];
    }
#pragma unroll
    for (int i = 0; i < 8; i++) {
        int row = bm + tm0 + i;
        float4 o;
        o.x = acc[i][0] * scl[0] + bb[0];
        o.y = acc[i][1] * scl[1] + bb[1];
        o.z = acc[i][2] * scl[2] + bb[2];
        o.w = acc[i][3] * scl[3] + bb[3];
        *(float4*)(&g_z[(size_t)row * FEAT + tn0]) = o;
    }
}

// ---------------- 3) s = z@a_src, d = z@a_dst (warp per row) -----------------
__global__ void sd_kernel(const float* __restrict__ att) {
    int w    = (blockIdx.x * blockDim.x + threadIdx.x) >> 5;
    int lane = threadIdx.x & 31;
    if (w >= NROW) return;
    const float* zr = g_z + (size_t)w * FEAT;
    float s = 0.f, d = 0.f;
#pragma unroll
    for (int q = 0; q < 4; q++) {
        int f = lane + q * 32;
        float zv = zr[f];
        s += zv * att[f];
        d += zv * att[FEAT + f];
    }
    for (int off = 16; off; off >>= 1) {
        s += __shfl_xor_sync(0xffffffffu, s, off);
        d += __shfl_xor_sync(0xffffffffu, d, off);
    }
    if (lane == 0) { g_s[w] = s; g_d[w] = d; }
}

// ---------------- 4) rank init + sortable key --------------------------------
__global__ void prep_kernel() {
    int i = blockIdx.x * 256 + threadIdx.x;
    if (i >= NROW) return;
    g_rank[i] = 0;
    unsigned int u = float_key(g_d[i]);
    g_dkey[i] = ((unsigned long long)u << 32) | (unsigned int)i;   // tie-break by index
}

// ---------------- 5) counting-sort ranks (key < key) -------------------------
__global__ void count_kernel() {
    __shared__ unsigned long long sk[1024];
    int j     = blockIdx.x * 256 + threadIdx.x;
    int cbase = blockIdx.y * 1024;
#pragma unroll
    for (int q = 0; q < 4; q++)
        sk[threadIdx.x + q * 256] = g_dkey[cbase + threadIdx.x + q * 256];
    __syncthreads();
    unsigned long long kj = g_dkey[j];
    int cnt = 0;
#pragma unroll 8
    for (int slot = 0; slot < 1024; slot++) cnt += (sk[slot] < kj) ? 1 : 0;
    atomicAdd(&g_rank[j], cnt);
}

// ---------------- 6) scatter z, d into sorted order --------------------------
__global__ void scatter_kernel() {
    int j = blockIdx.x;
    int f = threadIdx.x;
    int r = g_rank[j];
    g_zs[(size_t)r * FEAT + f] = g_z[(size_t)j * FEAT + f];
    if (f == 0) {
        float dv = g_d[j];
        g_sortedD[r] = dv;
        g_expD[r]    = expf(dv);
    }
}

// ---------------- 7) blocked scans: pass A (local) ---------------------------
__global__ void scanA_kernel() {
    int b    = blockIdx.x;
    int f    = threadIdx.x;   // 128
    int base = b * 256;

    float acc = 0.f;
    for (int t = 0; t < 256; t++) {
        int r = base + t;
        acc += g_zs[(size_t)r * FEAT + f];
        g_S0[(size_t)(r + 1) * FEAT + f] = acc;   // local inclusive -> global exclusive later
    }
    g_T0[b * FEAT + f] = acc;

    float accS = 0.f;
    for (int t = 255; t >= 0; t--) {
        int r = base + t;
        accS += g_expD[r] * g_zs[(size_t)r * FEAT + f];
        g_SufE[(size_t)r * FEAT + f] = accS;
    }
    g_TS[b * FEAT + f] = accS;

    // scalar suffix of expD within block (warp 0)
    __shared__ float se[256];
    se[f]       = g_expD[base + f];
    se[f + 128] = g_expD[base + f + 128];
    __syncthreads();
    if (f < 32) {
        float vals[8];
        float seg = 0.f;
#pragma unroll
        for (int q = 0; q < 8; q++) { vals[q] = se[f * 8 + q]; seg += vals[q]; }
        float suf = seg;
        for (int off = 16; off; off >>= 1) {
            float o = __shfl_down_sync(0xffffffffu, suf, off);
            if (f + off < 32) suf += o;
        }
        float run = suf - seg;   // exclusive suffix (lanes > f)
#pragma unroll
        for (int q = 7; q >= 0; q--) {
            run += vals[q];
            g_c1suf[base + f * 8 + q] = run;
        }
        if (f == 0) g_Tc[b] = suf;
    }
}

// ---------------- 8) pass B: scan the 48 block totals ------------------------
__global__ void scanB_kernel() {
    int f = threadIdx.x;   // 128
    float run = 0.f;
    for (int b2 = 0; b2 < NBLK; b2++) {
        g_off0[b2 * FEAT + f] = run;
        run += g_T0[b2 * FEAT + f];
    }
    g_S0[f] = 0.f;   // k = 0 row

    float run2 = 0.f;
    for (int b2 = NBLK - 1; b2 >= 0; b2--) {
        g_offS[b2 * FEAT + f] = run2;
        run2 += g_TS[b2 * FEAT + f];
    }
    g_SufE[(size_t)NROW * FEAT + f] = 0.f;   // k = N row

    if (f == 0) {
        float rc = 0.f;
        for (int b2 = NBLK - 1; b2 >= 0; b2--) {
            g_offc[b2] = rc;
            rc += g_Tc[b2];
        }
        g_c1suf[NROW] = 0.f;
    }
}

// ---------------- 9) pass C: apply block offsets ------------------------------
__global__ void scanC_kernel() {
    int b    = blockIdx.x;
    int base = b * 256;
    float offc = g_offc[b];
    for (int idx = threadIdx.x; idx < 256 * 128; idx += 256) {
        int rl = idx >> 7;
        int f  = idx & 127;
        int r  = base + rl;
        g_S0[(size_t)(r + 1) * FEAT + f] += g_off0[b * FEAT + f];
        g_SufE[(size_t)r * FEAT + f]     += g_offS[b * FEAT + f];
    }
    for (int r = threadIdx.x; r < 256; r += 256) g_c1suf[base + r] += offc;
}

// ---------------- 10) per-row split point k_i = #{d_j <= -s_i} ---------------
__global__ void findk_kernel() {
    int i = blockIdx.x * blockDim.x + threadIdx.x;
    if (i >= NROW) return;
    float t = -g_s[i];
    int lo = 0, hi = NROW;
    while (lo < hi) {
        int mid = (lo + hi) >> 1;
        if (g_sortedD[mid] <= t) lo = mid + 1;
        else hi = mid;
    }
    g_k[i] = lo;
}

// ---------------- 11) combine + final row softmax ----------------------------
__global__ void combine_kernel(float* __restrict__ out) {
    int i = blockIdx.x;
    int f = threadIdx.x;   // 128

    float s    = g_s[i];
    int   k    = g_k[i];
    float dmax = g_sortedD[NROW - 1];
    float m     = fmaxf(0.f, s + dmax);
    float alpha = expf(s - m);
    float beta  = expf(-m);
    float den   = alpha * g_c1suf[k] + beta * (float)k;

    size_t kb = (size_t)k * FEAT + f;
    float num = alpha * g_SufE[kb] + beta * g_S0[kb];
    float z2  = num / den + g_z[(size_t)i * FEAT + f];

    // softmax over 128
    __shared__ float red[4];
    float mx = z2;
    for (int off = 16; off; off >>= 1) mx = fmaxf(mx, __shfl_xor_sync(0xffffffffu, mx, off));
    if ((f & 31) == 0) red[f >> 5] = mx;
    __syncthreads();
    mx = fmaxf(fmaxf(red[0], red[1]), fmaxf(red[2], red[3]));
    float e = expf(z2 - mx);
    float sm = e;
    for (int off = 16; off; off >>= 1) sm += __shfl_xor_sync(0xffffffffu, sm, off);
    __syncthreads();
    if ((f & 31) == 0) red[f >> 5] = sm;
    __syncthreads();
    sm = red[0] + red[1] + red[2] + red[3];
    out[(size_t)i * FEAT + f] = e / sm;
}

// ---------------- launch ------------------------------------------------------
extern "C" void kernel_launch(void* const* d_in, const int* in_sizes, int n_in,
                              void* d_out, int out_size) {
    const float* x   = (const float*)d_in[0];   // [12288, 512]
    const float* v   = (const float*)d_in[1];   // [128, 512]
    const float* g   = (const float*)d_in[2];   // [128]
    const float* b   = (const float*)d_in[3];   // [128]
    const float* att = (const float*)d_in[4];   // [256]
    float* out = (float*)d_out;                 // [12288, 128]

    scale_kernel<<<FEAT, 128>>>(v, g);
    gemm_z_kernel<<<NROW / 64, 256>>>(x, v, b);
    sd_kernel<<<NROW / 8, 256>>>(att);
    prep_kernel<<<NBLK, 256>>>();
    count_kernel<<<dim3(NBLK, 12), 256>>>();
    scatter_kernel<<<NROW, 128>>>();
    scanA_kernel<<<NBLK, 128>>>();
    scanB_kernel<<<1, 128>>>();
    scanC_kernel<<<NBLK, 256>>>();
    findk_kernel<<<NBLK, 256>>>();
    combine_kernel<<<NROW, 128>>>(out);
}

// round 2
// speedup vs baseline: 1.1759x; 1.1759x over previous
#include <cuda_runtime.h>
#include <math.h>

#define NROW 12288
#define DIM  512
#define FEAT 128
#define TR   64            // rows per scan tile
#define NBR  192           // NROW / TR
#define CBLK 48            // NROW / 256

// ---------------- scratch (device globals; allocations forbidden) -----------
__device__ float g_scale[FEAT];
__device__ float g_vT[DIM * FEAT];           // transposed, scale-folded v
__device__ float g_z[NROW * FEAT];
__device__ float g_s[NROW];
__device__ float g_d[NROW];
__device__ unsigned long long g_dkey[NROW];
__device__ int   g_rank[NROW];
__device__ int   g_inv[NROW];
__device__ float g_sortedD[NROW];
__device__ float g_expD[NROW];
__device__ float g_S0[(NROW + 1) * FEAT];    // LOCAL exclusive prefix per 64-tile
__device__ float g_SufE[(NROW + 1) * FEAT];  // LOCAL inclusive suffix per 64-tile
__device__ float g_c1[NROW + 1];             // LOCAL suffix of expD per 64-tile
__device__ float g_T0[NBR * FEAT];
__device__ float g_TS[NBR * FEAT];
__device__ float g_Tc[NBR];
__device__ float g_off0[(NBR + 1) * FEAT];
__device__ float g_offS[(NBR + 1) * FEAT];
__device__ float g_offc[NBR + 1];

// ---------------- helpers ----------------------------------------------------
__device__ __forceinline__ unsigned int float_key(float x) {
    unsigned int u = __float_as_uint(x);
    return (u & 0x80000000u) ? ~u : (u | 0x80000000u);
}
__device__ __forceinline__ unsigned long long pack2(float lo, float hi) {
    unsigned long long r;
    asm("mov.b64 %0, {%1, %2};" : "=l"(r) : "f"(lo), "f"(hi));
    return r;
}
__device__ __forceinline__ void unpack2(float& lo, float& hi, unsigned long long v) {
    asm("mov.b64 {%0, %1}, %2;" : "=f"(lo), "=f"(hi) : "l"(v));
}
__device__ __forceinline__ void ffma2(unsigned long long& d, unsigned long long a,
                                      unsigned long long b) {
    asm("fma.rn.f32x2 %0, %1, %2, %0;" : "+l"(d) : "l"(a), "l"(b));
}

// ---------------- 1) scale[f] = g[f] / ||v_f|| -------------------------------
__global__ void scale_kernel(const float* __restrict__ v, const float* __restrict__ g) {
    int f = blockIdx.x;
    int t = threadIdx.x;
    float ss = 0.f;
    for (int q = t; q < DIM; q += 128) {
        float vv = v[(size_t)f * DIM + q];
        ss += vv * vv;
    }
    __shared__ float red[4];
    for (int off = 16; off; off >>= 1) ss += __shfl_xor_sync(0xffffffffu, ss, off);
    if ((t & 31) == 0) red[t >> 5] = ss;
    __syncthreads();
    if (t == 0) g_scale[f] = g[f] / sqrtf(red[0] + red[1] + red[2] + red[3]);
}

// ---------------- 2) vT[k][f] = v[f][k] * scale[f] ---------------------------
__global__ void vt_kernel(const float* __restrict__ v) {
    int k = blockIdx.x;
    int f = threadIdx.x;
    g_vT[k * FEAT + f] = v[(size_t)f * DIM + k] * g_scale[f];
}

// ---------------- 3) GEMM z = x@vT + b, fused s,d and sort keys --------------
// BM=64, BN=128, BK=32, 256 threads, thread tile 4x8, packed f32x2 FMAs.
__global__ void __launch_bounds__(256, 2) gemm_kernel(const float* __restrict__ x,
                                                      const float* __restrict__ b,
                                                      const float* __restrict__ att) {
    __shared__ float xs[64][36];     // row-major x tile, padded (conflict-free)
    __shared__ float vs[32][128];    // [kk][f]
    const int bm  = blockIdx.x * 64;
    const int tid = threadIdx.x;
    const int tn0 = (tid & 15) * 8;
    const int tm0 = (tid >> 4) * 4;

    unsigned long long acc[4][4];
    const unsigned long long z64 = pack2(0.f, 0.f);
#pragma unroll
    for (int i = 0; i < 4; i++)
#pragma unroll
        for (int p = 0; p < 4; p++) acc[i][p] = z64;

    for (int k0 = 0; k0 < DIM; k0 += 32) {
#pragma unroll
        for (int l = 0; l < 2; l++) {
            int li = tid + l * 256;
            int r  = li >> 3;
            int c4 = (li & 7) * 4;
            *(float4*)&xs[r][c4] = *(const float4*)(x + (size_t)(bm + r) * DIM + k0 + c4);
        }
#pragma unroll
        for (int l = 0; l < 4; l++) {
            int li = tid + l * 256;
            int kk = li >> 5;
            int f4 = (li & 31) * 4;
            *(float4*)&vs[kk][f4] = *(const float4*)(g_vT + (size_t)(k0 + kk) * FEAT + f4);
        }
        __syncthreads();
#pragma unroll
        for (int kk = 0; kk < 32; kk++) {
            ulonglong2 b0 = *(const ulonglong2*)&vs[kk][tn0];
            ulonglong2 b1 = *(const ulonglong2*)&vs[kk][tn0 + 4];
#pragma unroll
            for (int i = 0; i < 4; i++) {
                float a = xs[tm0 + i][kk];
                unsigned long long a2 = pack2(a, a);
                ffma2(acc[i][0], a2, b0.x);
                ffma2(acc[i][1], a2, b0.y);
                ffma2(acc[i][2], a2, b1.x);
                ffma2(acc[i][3], a2, b1.y);
            }
        }
        __syncthreads();
    }

    float bb[8], as[8], ad[8];
#pragma unroll
    for (int j = 0; j < 8; j++) {
        bb[j] = b[tn0 + j];
        as[j] = att[tn0 + j];
        ad[j] = att[FEAT + tn0 + j];
    }
#pragma unroll
    for (int i = 0; i < 4; i++) {
        float z8[8];
#pragma unroll
        for (int p = 0; p < 4; p++) unpack2(z8[2 * p], z8[2 * p + 1], acc[i][p]);
        float si = 0.f, di = 0.f;
#pragma unroll
        for (int j = 0; j < 8; j++) {
            z8[j] += bb[j];
            si += z8[j] * as[j];
            di += z8[j] * ad[j];
        }
        int row = bm + tm0 + i;
        float4 o0 = {z8[0], z8[1], z8[2], z8[3]};
        float4 o1 = {z8[4], z8[5], z8[6], z8[7]};
        *(float4*)&g_z[(size_t)row * FEAT + tn0]     = o0;
        *(float4*)&g_z[(size_t)row * FEAT + tn0 + 4] = o1;
#pragma unroll
        for (int off = 8; off; off >>= 1) {
            si += __shfl_xor_sync(0xffffffffu, si, off);
            di += __shfl_xor_sync(0xffffffffu, di, off);
        }
        if ((tid & 15) == 0) {
            g_s[row] = si;
            g_d[row] = di;
            unsigned int u = float_key(di);
            g_dkey[row] = ((unsigned long long)u << 32) | (unsigned int)row;
            g_rank[row] = 0;
        }
    }
}

// ---------------- 4) counting-sort ranks -------------------------------------
__global__ void count_kernel() {
    __shared__ unsigned long long sk[1024];
    int j     = blockIdx.x * 256 + threadIdx.x;
    int cbase = blockIdx.y * 1024;
#pragma unroll
    for (int q = 0; q < 4; q++)
        sk[threadIdx.x + q * 256] = g_dkey[cbase + threadIdx.x + q * 256];
    __syncthreads();
    unsigned long long kj = g_dkey[j];
    int cnt = 0;
#pragma unroll 8
    for (int slot = 0; slot < 1024; slot++) cnt += (sk[slot] < kj) ? 1 : 0;
    atomicAdd(&g_rank[j], cnt);
}

// ---------------- 5) inverse permutation + sorted d, expD --------------------
__global__ void invperm_kernel() {
    int i = blockIdx.x * 256 + threadIdx.x;
    int r = g_rank[i];
    float d = g_d[i];
    g_inv[r]     = i;
    g_sortedD[r] = d;
    g_expD[r]    = expf(d);
}

// ---------------- 6) local scans per 64-row tile (gather via inv perm) -------
__global__ void scanA_kernel() {
    int b    = blockIdx.x;
    int f    = threadIdx.x;   // 128
    int base = b * TR;
    __shared__ int   jidx[TR];
    __shared__ float ed[TR];
    if (f < TR) {
        jidx[f] = g_inv[base + f];
        ed[f]   = g_expD[base + f];
    }
    __syncthreads();

    float acc = 0.f;
    for (int t = 0; t < TR; t++) {
        g_S0[(size_t)(base + t) * FEAT + f] = acc;       // local exclusive
        acc += g_z[(size_t)jidx[t] * FEAT + f];
    }
    g_T0[b * FEAT + f] = acc;

    float accS = 0.f;
    for (int t = TR - 1; t >= 0; t--) {
        accS += ed[t] * g_z[(size_t)jidx[t] * FEAT + f];
        g_SufE[(size_t)(base + t) * FEAT + f] = accS;    // local inclusive suffix
    }
    g_TS[b * FEAT + f] = accS;

    if (f < 32) {
        float v0 = ed[2 * f], v1 = ed[2 * f + 1];
        float seg = v0 + v1;
        float suf = seg;
#pragma unroll
        for (int off = 1; off < 32; off <<= 1) {
            float t2 = __shfl_down_sync(0xffffffffu, suf, off);
            if (f + off < 32) suf += t2;
        }
        float excl = suf - seg;
        g_c1[base + 2 * f + 1] = excl + v1;
        g_c1[base + 2 * f]     = excl + v1 + v0;
        if (f == 0) g_Tc[b] = suf;
    }
}

// ---------------- 7) scan the 192 tile totals into offset tables -------------
__global__ void scanB_kernel() {
    int f = threadIdx.x;   // 128
    float run = 0.f;
    for (int b2 = 0; b2 < NBR; b2++) {
        g_off0[b2 * FEAT + f] = run;
        run += g_T0[b2 * FEAT + f];
    }
    g_off0[NBR * FEAT + f] = run;
    g_S0[(size_t)NROW * FEAT + f] = 0.f;

    float run2 = 0.f;
    g_offS[NBR * FEAT + f] = 0.f;
    for (int b2 = NBR - 1; b2 >= 0; b2--) {
        g_offS[b2 * FEAT + f] = run2;
        run2 += g_TS[b2 * FEAT + f];
    }
    g_SufE[(size_t)NROW * FEAT + f] = 0.f;

    if (f < 32) {
        float vals[6];
        float seg = 0.f;
#pragma unroll
        for (int q = 0; q < 6; q++) { vals[q] = g_Tc[f * 6 + q]; seg += vals[q]; }
        float suf = seg;
#pragma unroll
        for (int off = 1; off < 32; off <<= 1) {
            float t2 = __shfl_down_sync(0xffffffffu, suf, off);
            if (f + off < 32) suf += t2;
        }
        float run3 = suf - seg;   // sum over lanes > f
#pragma unroll
        for (int q = 5; q >= 0; q--) {
            g_offc[f * 6 + q] = run3;
            run3 += vals[q];
        }
        if (f == 0) { g_offc[NBR] = 0.f; g_c1[NROW] = 0.f; }
    }
}

// ---------------- 8) combine: binary search + rank-1 softmax + row softmax ---
__global__ void combine_kernel(float* __restrict__ out) {
    int i = blockIdx.x;
    int f = threadIdx.x;   // 128

    float s = g_s[i];
    float thr = -s;
    int lo = 0, hi = NROW;
#pragma unroll 1
    while (lo < hi) {
        int mid = (lo + hi) >> 1;
        if (g_sortedD[mid] <= thr) lo = mid + 1;
        else hi = mid;
    }
    int k   = lo;
    int blk = k >> 6;

    float dmax  = g_sortedD[NROW - 1];
    float m     = fmaxf(0.f, s + dmax);
    float alpha = expf(s - m);
    float beta  = expf(-m);
    float den   = alpha * (g_offc[blk] + g_c1[k]) + beta * (float)k;

    size_t kb = (size_t)k * FEAT + f;
    size_t ob = (size_t)blk * FEAT + f;
    float num = alpha * (g_offS[ob] + g_SufE[kb]) + beta * (g_off0[ob] + g_S0[kb]);
    float z2  = num / den + g_z[(size_t)i * FEAT + f];

    __shared__ float red[4];
    float mx = z2;
    for (int off = 16; off; off >>= 1) mx = fmaxf(mx, __shfl_xor_sync(0xffffffffu, mx, off));
    if ((f & 31) == 0) red[f >> 5] = mx;
    __syncthreads();
    mx = fmaxf(fmaxf(red[0], red[1]), fmaxf(red[2], red[3]));
    float e = expf(z2 - mx);
    float sm = e;
    for (int off = 16; off; off >>= 1) sm += __shfl_xor_sync(0xffffffffu, sm, off);
    __syncthreads();
    if ((f & 31) == 0) red[f >> 5] = sm;
    __syncthreads();
    sm = red[0] + red[1] + red[2] + red[3];
    out[(size_t)i * FEAT + f] = e / sm;
}

// ---------------- launch ------------------------------------------------------
extern "C" void kernel_launch(void* const* d_in, const int* in_sizes, int n_in,
                              void* d_out, int out_size) {
    const float* x   = (const float*)d_in[0];   // [12288, 512]
    const float* v   = (const float*)d_in[1];   // [128, 512]
    const float* g   = (const float*)d_in[2];   // [128]
    const float* b   = (const float*)d_in[3];   // [128]
    const float* att = (const float*)d_in[4];   // [256]
    float* out = (float*)d_out;                 // [12288, 128]

    scale_kernel<<<FEAT, 128>>>(v, g);
    vt_kernel<<<DIM, 128>>>(v);
    gemm_kernel<<<NROW / 64, 256>>>(x, b, att);
    count_kernel<<<dim3(CBLK, 12), 256>>>();
    invperm_kernel<<<CBLK, 256>>>();
    scanA_kernel<<<NBR, 128>>>();
    scanB_kernel<<<1, 128>>>();
    combine_kernel<<<NROW, 128>>>(out);
}

// round 5
// speedup vs baseline: 1.4985x; 1.2743x over previous
#include <cuda_runtime.h>
#include <cuda_bf16.h>
#include <math.h>
#include <stdint.h>

#define NROW 12288
#define DIM  512
#define FEAT 128
#define TR   64            // rows per scan tile
#define NBR  192           // NROW / TR
#define CBLK 48            // NROW / 256
#define SA   72            // padded bf16 row stride in smem (conflict-free)

// ---------------- scratch (device globals; allocations forbidden) -----------
__device__ float g_scale[FEAT];
__device__ unsigned short g_vhi[FEAT * DIM];
__device__ unsigned short g_vlo[FEAT * DIM];
__device__ unsigned short g_xhi[NROW * DIM];
__device__ unsigned short g_xlo[NROW * DIM];
__device__ float g_z[NROW * FEAT];
__device__ float g_s[NROW];
__device__ float g_d[NROW];
__device__ unsigned long long g_dkey[NROW];
__device__ int   g_rank[NROW];
__device__ int   g_inv[NROW];
__device__ float g_sortedD[NROW];
__device__ float g_expD[NROW];
__device__ float g_S0[(NROW + 1) * FEAT];
__device__ float g_SufE[(NROW + 1) * FEAT];
__device__ float g_c1[NROW + 1];
__device__ float g_T0[NBR * FEAT];
__device__ float g_TS[NBR * FEAT];
__device__ float g_Tc[NBR];
__device__ float g_off0[(NBR + 1) * FEAT];
__device__ float g_offS[(NBR + 1) * FEAT];
__device__ float g_offc[NBR + 1];

// ---------------- helpers -----------------------------------------------------
__device__ __forceinline__ unsigned int float_key(float x) {
    unsigned int u = __float_as_uint(x);
    return (u & 0x80000000u) ? ~u : (u | 0x80000000u);
}
__device__ __forceinline__ void mma_bf16(float* c, const uint32_t* a,
                                         uint32_t b0, uint32_t b1) {
    asm volatile(
        "mma.sync.aligned.m16n8k16.row.col.f32.bf16.bf16.f32 "
        "{%0,%1,%2,%3}, {%4,%5,%6,%7}, {%8,%9}, {%0,%1,%2,%3};"
        : "+f"(c[0]), "+f"(c[1]), "+f"(c[2]), "+f"(c[3])
        : "r"(a[0]), "r"(a[1]), "r"(a[2]), "r"(a[3]), "r"(b0), "r"(b1));
}

// ---------------- 1) scale[f] = g[f] / ||v_f|| -------------------------------
__global__ void scale_kernel(const float* __restrict__ v, const float* __restrict__ g) {
    int f = blockIdx.x;
    int t = threadIdx.x;
    float ss = 0.f;
    for (int q = t; q < DIM; q += 128) {
        float vv = v[(size_t)f * DIM + q];
        ss += vv * vv;
    }
    __shared__ float red[4];
    for (int off = 16; off; off >>= 1) ss += __shfl_xor_sync(0xffffffffu, ss, off);
    if ((t & 31) == 0) red[t >> 5] = ss;
    __syncthreads();
    if (t == 0) g_scale[f] = g[f] / sqrtf(red[0] + red[1] + red[2] + red[3]);
}

// ---------------- 2) split scaled v into bf16 hi/lo --------------------------
__global__ void vsplit_kernel(const float* __restrict__ v) {
    int f = blockIdx.x;
    int t = threadIdx.x;
    float sc = g_scale[f];
    for (int k = t; k < DIM; k += 128) {
        float val = v[(size_t)f * DIM + k] * sc;
        __nv_bfloat16 h = __float2bfloat16(val);
        float lo = val - __bfloat162float(h);
        g_vhi[f * DIM + k] = __bfloat16_as_ushort(h);
        g_vlo[f * DIM + k] = __bfloat16_as_ushort(__float2bfloat16(lo));
    }
}

// ---------------- 3) split x into bf16 hi/lo ---------------------------------
__global__ void xsplit_kernel(const float* __restrict__ x) {
    size_t i = (size_t)blockIdx.x * 256 + threadIdx.x;   // float4 index
    float4 xv = *((const float4*)x + i);
    __nv_bfloat16 h0 = __float2bfloat16(xv.x);
    __nv_bfloat16 h1 = __float2bfloat16(xv.y);
    __nv_bfloat16 h2 = __float2bfloat16(xv.z);
    __nv_bfloat16 h3 = __float2bfloat16(xv.w);
    uint2 hv, lv;
    hv.x = ((uint32_t)__bfloat16_as_ushort(h1) << 16) | __bfloat16_as_ushort(h0);
    hv.y = ((uint32_t)__bfloat16_as_ushort(h3) << 16) | __bfloat16_as_ushort(h2);
    __nv_bfloat16 l0 = __float2bfloat16(xv.x - __bfloat162float(h0));
    __nv_bfloat16 l1 = __float2bfloat16(xv.y - __bfloat162float(h1));
    __nv_bfloat16 l2 = __float2bfloat16(xv.z - __bfloat162float(h2));
    __nv_bfloat16 l3 = __float2bfloat16(xv.w - __bfloat162float(h3));
    lv.x = ((uint32_t)__bfloat16_as_ushort(l1) << 16) | __bfloat16_as_ushort(l0);
    lv.y = ((uint32_t)__bfloat16_as_ushort(l3) << 16) | __bfloat16_as_ushort(l2);
    *(uint2*)(g_xhi + i * 4) = hv;
    *(uint2*)(g_xlo + i * 4) = lv;
}

// ---------------- 4) HMMA GEMM z = x@v'^T + b, fused epilogue ----------------
// CTA: 128 threads (4 warps). Tile 128x128, K-chunks of 64 in smem.
// Warp w: rows [w*32, w*32+32) as two m16 tiles; full N=128 as 16 n8 tiles.
__global__ void __launch_bounds__(128, 1) gemm_mma_kernel(const float* __restrict__ b,
                                                          const float* __restrict__ att) {
    extern __shared__ unsigned short sm[];
    unsigned short* aH = sm;
    unsigned short* aL = sm + 128 * SA;
    unsigned short* bH = sm + 2 * 128 * SA;
    unsigned short* bL = sm + 3 * 128 * SA;

    const int tid  = threadIdx.x;
    const int w    = tid >> 5;
    const int lane = tid & 31;
    const int g    = lane >> 2;
    const int tig  = lane & 3;
    const int bm   = blockIdx.x * 128;

    const int fr = tid >> 3;     // 16 rows per load pass
    const int ko = tid & 7;      // 16-byte unit within 64-k chunk (8 units = 64 cols)

    float acc[2][16][4];
#pragma unroll
    for (int mi = 0; mi < 2; mi++)
#pragma unroll
        for (int nt = 0; nt < 16; nt++)
#pragma unroll
            for (int q = 0; q < 4; q++) acc[mi][nt][q] = 0.f;

    for (int c = 0; c < 8; c++) {
        const int k0 = c * 64;
        // ---- stage chunk into smem (FULL 64-column coverage via uint4) ----
#pragma unroll
        for (int rp = 0; rp < 8; rp++) {
            int r = rp * 16 + fr;
            size_t gx = (size_t)(bm + r) * DIM + k0 + ko * 8;
            size_t gv = (size_t)r * DIM + k0 + ko * 8;
            *(uint4*)&aH[r * SA + ko * 8] = *(const uint4*)&g_xhi[gx];
            *(uint4*)&aL[r * SA + ko * 8] = *(const uint4*)&g_xlo[gx];
            *(uint4*)&bH[r * SA + ko * 8] = *(const uint4*)&g_vhi[gv];
            *(uint4*)&bL[r * SA + ko * 8] = *(const uint4*)&g_vlo[gv];
        }
        __syncthreads();

        // ---- compute 4 k16 tiles ----
#pragma unroll
        for (int kt = 0; kt < 4; kt++) {
            const int kb = kt * 16 + tig * 2;   // bf16 column of a0/b0
            uint32_t ah[2][4], al[2][4];
#pragma unroll
            for (int mi = 0; mi < 2; mi++) {
                int rb = w * 32 + mi * 16;
                ah[mi][0] = *(const uint32_t*)&aH[(rb + g) * SA + kb];
                ah[mi][1] = *(const uint32_t*)&aH[(rb + g + 8) * SA + kb];
                ah[mi][2] = *(const uint32_t*)&aH[(rb + g) * SA + kb + 8];
                ah[mi][3] = *(const uint32_t*)&aH[(rb + g + 8) * SA + kb + 8];
                al[mi][0] = *(const uint32_t*)&aL[(rb + g) * SA + kb];
                al[mi][1] = *(const uint32_t*)&aL[(rb + g + 8) * SA + kb];
                al[mi][2] = *(const uint32_t*)&aL[(rb + g) * SA + kb + 8];
                al[mi][3] = *(const uint32_t*)&aL[(rb + g + 8) * SA + kb + 8];
            }
#pragma unroll
            for (int nt = 0; nt < 16; nt++) {
                int nr = nt * 8 + g;
                uint32_t bh0 = *(const uint32_t*)&bH[nr * SA + kb];
                uint32_t bh1 = *(const uint32_t*)&bH[nr * SA + kb + 8];
                uint32_t bl0 = *(const uint32_t*)&bL[nr * SA + kb];
                uint32_t bl1 = *(const uint32_t*)&bL[nr * SA + kb + 8];
#pragma unroll
                for (int mi = 0; mi < 2; mi++) {
                    mma_bf16(acc[mi][nt], ah[mi], bh0, bh1);
                    mma_bf16(acc[mi][nt], ah[mi], bl0, bl1);
                    mma_bf16(acc[mi][nt], al[mi], bh0, bh1);
                }
            }
        }
        __syncthreads();
    }

    // ---- epilogue: z = acc + b; fused s,d; store keys ----
    float sv[2][2] = {{0.f, 0.f}, {0.f, 0.f}};
    float dv[2][2] = {{0.f, 0.f}, {0.f, 0.f}};
#pragma unroll
    for (int mi = 0; mi < 2; mi++) {
        int rb = bm + w * 32 + mi * 16;
#pragma unroll
        for (int nt = 0; nt < 16; nt++) {
            int c0 = nt * 8 + tig * 2;
            float2 bb = *(const float2*)&b[c0];
            float2 as = *(const float2*)&att[c0];
            float2 ad = *(const float2*)&att[FEAT + c0];
            float z0 = acc[mi][nt][0] + bb.x;
            float z1 = acc[mi][nt][1] + bb.y;
            float z2 = acc[mi][nt][2] + bb.x;
            float z3 = acc[mi][nt][3] + bb.y;
            *(float2*)&g_z[(size_t)(rb + g) * FEAT + c0]     = make_float2(z0, z1);
            *(float2*)&g_z[(size_t)(rb + g + 8) * FEAT + c0] = make_float2(z2, z3);
            sv[mi][0] += z0 * as.x + z1 * as.y;
            sv[mi][1] += z2 * as.x + z3 * as.y;
            dv[mi][0] += z0 * ad.x + z1 * ad.y;
            dv[mi][1] += z2 * ad.x + z3 * ad.y;
        }
    }
#pragma unroll
    for (int mi = 0; mi < 2; mi++)
#pragma unroll
        for (int h = 0; h < 2; h++) {
            float s = sv[mi][h], d = dv[mi][h];
            s += __shfl_xor_sync(0xffffffffu, s, 1);
            s += __shfl_xor_sync(0xffffffffu, s, 2);
            d += __shfl_xor_sync(0xffffffffu, d, 1);
            d += __shfl_xor_sync(0xffffffffu, d, 2);
            if (tig == 0) {
                int row = bm + w * 32 + mi * 16 + h * 8 + g;
                g_s[row] = s;
                g_d[row] = d;
                unsigned int u = float_key(d);
                g_dkey[row] = ((unsigned long long)u << 32) | (unsigned int)row;
                g_rank[row] = 0;
            }
        }
}

// ---------------- 5) counting-sort ranks -------------------------------------
__global__ void count_kernel() {
    __shared__ unsigned long long sk[1024];
    int j     = blockIdx.x * 256 + threadIdx.x;
    int cbase = blockIdx.y * 1024;
#pragma unroll
    for (int q = 0; q < 4; q++)
        sk[threadIdx.x + q * 256] = g_dkey[cbase + threadIdx.x + q * 256];
    __syncthreads();
    unsigned long long kj = g_dkey[j];
    int cnt = 0;
#pragma unroll 8
    for (int slot = 0; slot < 1024; slot++) cnt += (sk[slot] < kj) ? 1 : 0;
    atomicAdd(&g_rank[j], cnt);
}

// ---------------- 6) inverse permutation + sorted d, expD --------------------
__global__ void invperm_kernel() {
    int i = blockIdx.x * 256 + threadIdx.x;
    int r = g_rank[i];
    float d = g_d[i];
    g_inv[r]     = i;
    g_sortedD[r] = d;
    g_expD[r]    = expf(d);
}

// ---------------- 7) local scans per 64-row tile -----------------------------
__global__ void scanA_kernel() {
    int b    = blockIdx.x;
    int f    = threadIdx.x;   // 128
    int base = b * TR;
    __shared__ int   jidx[TR];
    __shared__ float ed[TR];
    if (f < TR) {
        jidx[f] = g_inv[base + f];
        ed[f]   = g_expD[base + f];
    }
    __syncthreads();

    float acc = 0.f;
    for (int t = 0; t < TR; t++) {
        g_S0[(size_t)(base + t) * FEAT + f] = acc;
        acc += g_z[(size_t)jidx[t] * FEAT + f];
    }
    g_T0[b * FEAT + f] = acc;

    float accS = 0.f;
    for (int t = TR - 1; t >= 0; t--) {
        accS += ed[t] * g_z[(size_t)jidx[t] * FEAT + f];
        g_SufE[(size_t)(base + t) * FEAT + f] = accS;
    }
    g_TS[b * FEAT + f] = accS;

    if (f < 32) {
        float v0 = ed[2 * f], v1 = ed[2 * f + 1];
        float seg = v0 + v1;
        float suf = seg;
#pragma unroll
        for (int off = 1; off < 32; off <<= 1) {
            float t2 = __shfl_down_sync(0xffffffffu, suf, off);
            if (f + off < 32) suf += t2;
        }
        float excl = suf - seg;
        g_c1[base + 2 * f + 1] = excl + v1;
        g_c1[base + 2 * f]     = excl + v1 + v0;
        if (f == 0) g_Tc[b] = suf;
    }
}

// ---------------- 8) scan tile totals ----------------------------------------
__global__ void scanB_kernel() {
    int f = threadIdx.x;   // 128
    float run = 0.f;
    for (int b2 = 0; b2 < NBR; b2++) {
        g_off0[b2 * FEAT + f] = run;
        run += g_T0[b2 * FEAT + f];
    }
    g_off0[NBR * FEAT + f] = run;
    g_S0[(size_t)NROW * FEAT + f] = 0.f;

    float run2 = 0.f;
    g_offS[NBR * FEAT + f] = 0.f;
    for (int b2 = NBR - 1; b2 >= 0; b2--) {
        g_offS[b2 * FEAT + f] = run2;
        run2 += g_TS[b2 * FEAT + f];
    }
    g_SufE[(size_t)NROW * FEAT + f] = 0.f;

    if (f < 32) {
        float vals[6];
        float seg = 0.f;
#pragma unroll
        for (int q = 0; q < 6; q++) { vals[q] = g_Tc[f * 6 + q]; seg += vals[q]; }
        float suf = seg;
#pragma unroll
        for (int off = 1; off < 32; off <<= 1) {
            float t2 = __shfl_down_sync(0xffffffffu, suf, off);
            if (f + off < 32) suf += t2;
        }
        float run3 = suf - seg;
#pragma unroll
        for (int q = 5; q >= 0; q--) {
            g_offc[f * 6 + q] = run3;
            run3 += vals[q];
        }
        if (f == 0) { g_offc[NBR] = 0.f; g_c1[NROW] = 0.f; }
    }
}

// ---------------- 9) combine + final row softmax -----------------------------
__global__ void combine_kernel(float* __restrict__ out) {
    int i = blockIdx.x;
    int f = threadIdx.x;   // 128

    float s = g_s[i];
    float thr = -s;
    int lo = 0, hi = NROW;
#pragma unroll 1
    while (lo < hi) {
        int mid = (lo + hi) >> 1;
        if (g_sortedD[mid] <= thr) lo = mid + 1;
        else hi = mid;
    }
    int k   = lo;
    int blk = k >> 6;

    float dmax  = g_sortedD[NROW - 1];
    float m     = fmaxf(0.f, s + dmax);
    float alpha = expf(s - m);
    float beta  = expf(-m);
    float den   = alpha * (g_offc[blk] + g_c1[k]) + beta * (float)k;

    size_t kb = (size_t)k * FEAT + f;
    size_t ob = (size_t)blk * FEAT + f;
    float num = alpha * (g_offS[ob] + g_SufE[kb]) + beta * (g_off0[ob] + g_S0[kb]);
    float z2  = num / den + g_z[(size_t)i * FEAT + f];

    __shared__ float red[4];
    float mx = z2;
    for (int off = 16; off; off >>= 1) mx = fmaxf(mx, __shfl_xor_sync(0xffffffffu, mx, off));
    if ((f & 31) == 0) red[f >> 5] = mx;
    __syncthreads();
    mx = fmaxf(fmaxf(red[0], red[1]), fmaxf(red[2], red[3]));
    float e = expf(z2 - mx);
    float sm = e;
    for (int off = 16; off; off >>= 1) sm += __shfl_xor_sync(0xffffffffu, sm, off);
    __syncthreads();
    if ((f & 31) == 0) red[f >> 5] = sm;
    __syncthreads();
    sm = red[0] + red[1] + red[2] + red[3];
    out[(size_t)i * FEAT + f] = e / sm;
}

// ---------------- launch ------------------------------------------------------
extern "C" void kernel_launch(void* const* d_in, const int* in_sizes, int n_in,
                              void* d_out, int out_size) {
    const float* x   = (const float*)d_in[0];   // [12288, 512]
    const float* v   = (const float*)d_in[1];   // [128, 512]
    const float* g   = (const float*)d_in[2];   // [128]
    const float* b   = (const float*)d_in[3];   // [128]
    const float* att = (const float*)d_in[4];   // [256]
    float* out = (float*)d_out;                 // [12288, 128]

    const int smem = 4 * 128 * SA * 2;   // 73728 bytes
    cudaFuncSetAttribute(gemm_mma_kernel, cudaFuncAttributeMaxDynamicSharedMemorySize, smem);

    scale_kernel<<<FEAT, 128>>>(v, g);
    vsplit_kernel<<<FEAT, 128>>>(v);
    xsplit_kernel<<<NROW * DIM / 4 / 256, 256>>>(x);
    gemm_mma_kernel<<<NROW / 128, 128, smem>>>(b, att);
    count_kernel<<<dim3(CBLK, 12), 256>>>();
    invperm_kernel<<<CBLK, 256>>>();
    scanA_kernel<<<NBR, 128>>>();
    scanB_kernel<<<1, 128>>>();
    combine_kernel<<<NROW, 128>>>(out);
}

// round 6
// speedup vs baseline: 1.6435x; 1.0968x over previous
#include <cuda_runtime.h>
#include <cuda_bf16.h>
#include <math.h>
#include <stdint.h>

#define NROW 12288
#define DIM  512
#define FEAT 128
#define TR   64            // rows per scan tile
#define NBR  192           // NROW / TR
#define CBLK 48            // NROW / 256
#define SA   72            // padded bf16 row stride in smem (conflict-free)
#define NBUK 4096

// ---------------- scratch (device globals; allocations forbidden) -----------
__device__ float g_scale[FEAT];
__device__ unsigned short g_vhi[FEAT * DIM];
__device__ unsigned short g_vlo[FEAT * DIM];
__device__ float g_z[NROW * FEAT];
__device__ float g_s[NROW];
__device__ float g_d[NROW];
__device__ unsigned long long g_dkey[NROW];
__device__ int   g_bin[NROW];
__device__ int   g_hist[NBUK];
__device__ int   g_hcur[NBUK];
__device__ int   g_hstart[NBUK];
__device__ unsigned long long g_bkeys[NROW];
__device__ unsigned int g_kmin, g_kmax;
__device__ int   g_inv[NROW];
__device__ float g_sortedD[NROW];
__device__ float g_expD[NROW];
__device__ float g_S0[(NROW + 1) * FEAT];
__device__ float g_SufE[(NROW + 1) * FEAT];
__device__ float g_c1[NROW + 1];
__device__ float g_T0[NBR * FEAT];
__device__ float g_TS[NBR * FEAT];
__device__ float g_Tc[NBR];
__device__ float g_off0[(NBR + 1) * FEAT];
__device__ float g_offS[(NBR + 1) * FEAT];
__device__ float g_offc[NBR + 1];

// ---------------- helpers -----------------------------------------------------
__device__ __forceinline__ unsigned int float_key(float x) {
    unsigned int u = __float_as_uint(x);
    return (u & 0x80000000u) ? ~u : (u | 0x80000000u);
}
__device__ __forceinline__ uint32_t smem_u32(const void* p) {
    uint32_t a;
    asm("{ .reg .u64 t; cvta.to.shared.u64 t, %1; cvt.u32.u64 %0, t; }" : "=r"(a) : "l"(p));
    return a;
}
__device__ __forceinline__ void mma_bf16(float* c, const uint32_t* a,
                                         uint32_t b0, uint32_t b1) {
    asm volatile(
        "mma.sync.aligned.m16n8k16.row.col.f32.bf16.bf16.f32 "
        "{%0,%1,%2,%3}, {%4,%5,%6,%7}, {%8,%9}, {%0,%1,%2,%3};"
        : "+f"(c[0]), "+f"(c[1]), "+f"(c[2]), "+f"(c[3])
        : "r"(a[0]), "r"(a[1]), "r"(a[2]), "r"(a[3]), "r"(b0), "r"(b1));
}
#define LDSM4(r, addr) \
    asm volatile("ldmatrix.sync.aligned.m8n8.x4.shared.b16 {%0,%1,%2,%3}, [%4];" \
        : "=r"((r)[0]), "=r"((r)[1]), "=r"((r)[2]), "=r"((r)[3]) : "r"(addr))

// ---------------- 1) scale + zero hist/hcur + reset minmax -------------------
__global__ void scale_kernel(const float* __restrict__ v, const float* __restrict__ g) {
    int f = blockIdx.x;
    int t = threadIdx.x;
    int idx = f * 128 + t;
    if (idx < NBUK) g_hist[idx] = 0;
    else if (idx < 2 * NBUK) g_hcur[idx - NBUK] = 0;
    else if (idx == 2 * NBUK) { g_kmin = 0xFFFFFFFFu; g_kmax = 0u; }

    float ss = 0.f;
    for (int q = t; q < DIM; q += 128) {
        float vv = v[(size_t)f * DIM + q];
        ss += vv * vv;
    }
    __shared__ float red[4];
    for (int off = 16; off; off >>= 1) ss += __shfl_xor_sync(0xffffffffu, ss, off);
    if ((t & 31) == 0) red[t >> 5] = ss;
    __syncthreads();
    if (t == 0) g_scale[f] = g[f] / sqrtf(red[0] + red[1] + red[2] + red[3]);
}

// ---------------- 2) split scaled v into bf16 hi/lo --------------------------
__global__ void vsplit_kernel(const float* __restrict__ v) {
    int f = blockIdx.x;
    int t = threadIdx.x;
    float sc = g_scale[f];
    for (int k = t; k < DIM; k += 128) {
        float val = v[(size_t)f * DIM + k] * sc;
        __nv_bfloat16 h = __float2bfloat16(val);
        float lo = val - __bfloat162float(h);
        g_vhi[f * DIM + k] = __bfloat16_as_ushort(h);
        g_vlo[f * DIM + k] = __bfloat16_as_ushort(__float2bfloat16(lo));
    }
}

// ---------------- 3) HMMA GEMM z = x@v'^T + b, fused epilogue ----------------
// 192 CTAs x 256 threads (8 warps). Tile 64x128, K-chunks of 64.
// Warp (mw = w&3, nw = w>>2): rows mw*16..+16, cols nw*64..+64.
__global__ void __launch_bounds__(256) gemm_mma_kernel(const float* __restrict__ x,
                                                       const float* __restrict__ b,
                                                       const float* __restrict__ att) {
    extern __shared__ unsigned short sm[];
    unsigned short* aH = sm;                       // 64*SA
    unsigned short* aL = sm + 64 * SA;
    unsigned short* bH = sm + 2 * 64 * SA;         // 128*SA
    unsigned short* bL = sm + 2 * 64 * SA + 128 * SA;
    float* sdp = (float*)sm;                       // reused after mainloop

    const int tid  = threadIdx.x;
    const int w    = tid >> 5;
    const int lane = tid & 31;
    const int g    = lane >> 2;
    const int tig  = lane & 3;
    const int mw   = w & 3;
    const int nw   = w >> 2;
    const int bm   = blockIdx.x * 64;
    const int rb   = mw * 16;
    const int n0   = nw * 64;

    const uint32_t aHs = smem_u32(aH), aLs = smem_u32(aL);
    const uint32_t bHs = smem_u32(bH), bLs = smem_u32(bL);

    // ldmatrix lane addresses
    const int rA = (lane & 7) + ((lane >> 3) & 1) * 8;
    const int cA = (lane >> 4) * 8;
    const uint32_t aAdH = aHs + ((rb + rA) * SA + cA) * 2;
    const uint32_t aAdL = aLs + ((rb + rA) * SA + cA) * 2;
    const int rB = (lane & 7) + (lane >> 4) * 8;
    const int cB = ((lane >> 3) & 1) * 8;
    uint32_t bAdH[4], bAdL[4];
#pragma unroll
    for (int j = 0; j < 4; j++) {
        bAdH[j] = bHs + ((n0 + j * 16 + rB) * SA + cB) * 2;
        bAdL[j] = bLs + ((n0 + j * 16 + rB) * SA + cB) * 2;
    }

    float acc[8][4];
#pragma unroll
    for (int nt = 0; nt < 8; nt++)
#pragma unroll
        for (int q = 0; q < 4; q++) acc[nt][q] = 0.f;

    for (int c = 0; c < 8; c++) {
        const int k0 = c * 64;
        // ---- stage A: 64x64 fp32 -> bf16 hi/lo (1024 float4, 4/thread) ----
#pragma unroll
        for (int p = 0; p < 4; p++) {
            int li = tid + p * 256;
            int r  = li >> 4;
            int c4 = (li & 15) * 4;
            float4 xv = *(const float4*)(x + (size_t)(bm + r) * DIM + k0 + c4);
            __nv_bfloat16 h0 = __float2bfloat16(xv.x);
            __nv_bfloat16 h1 = __float2bfloat16(xv.y);
            __nv_bfloat16 h2 = __float2bfloat16(xv.z);
            __nv_bfloat16 h3 = __float2bfloat16(xv.w);
            uint2 hv, lv;
            hv.x = ((uint32_t)__bfloat16_as_ushort(h1) << 16) | __bfloat16_as_ushort(h0);
            hv.y = ((uint32_t)__bfloat16_as_ushort(h3) << 16) | __bfloat16_as_ushort(h2);
            __nv_bfloat16 l0 = __float2bfloat16(xv.x - __bfloat162float(h0));
            __nv_bfloat16 l1 = __float2bfloat16(xv.y - __bfloat162float(h1));
            __nv_bfloat16 l2 = __float2bfloat16(xv.z - __bfloat162float(h2));
            __nv_bfloat16 l3 = __float2bfloat16(xv.w - __bfloat162float(h3));
            lv.x = ((uint32_t)__bfloat16_as_ushort(l1) << 16) | __bfloat16_as_ushort(l0);
            lv.y = ((uint32_t)__bfloat16_as_ushort(l3) << 16) | __bfloat16_as_ushort(l2);
            *(uint2*)&aH[r * SA + c4] = hv;
            *(uint2*)&aL[r * SA + c4] = lv;
        }
        // ---- stage B: 128x64 bf16 x2 (1024 uint4 each, 4/thread each) ----
#pragma unroll
        for (int p = 0; p < 4; p++) {
            int li = tid + p * 256;
            int r  = li >> 3;
            int u  = li & 7;
            size_t gv = (size_t)r * DIM + k0 + u * 8;
            *(uint4*)&bH[r * SA + u * 8] = *(const uint4*)&g_vhi[gv];
            *(uint4*)&bL[r * SA + u * 8] = *(const uint4*)&g_vlo[gv];
        }
        __syncthreads();

#pragma unroll
        for (int kt = 0; kt < 4; kt++) {
            uint32_t ah[4], al[4];
            LDSM4(ah, aAdH + kt * 32);
            LDSM4(al, aAdL + kt * 32);
#pragma unroll
            for (int j = 0; j < 4; j++) {
                uint32_t bh[4], bl[4];
                LDSM4(bh, bAdH[j] + kt * 32);
                LDSM4(bl, bAdL[j] + kt * 32);
                mma_bf16(acc[2 * j],     ah, bh[0], bh[1]);
                mma_bf16(acc[2 * j],     ah, bl[0], bl[1]);
                mma_bf16(acc[2 * j],     al, bh[0], bh[1]);
                mma_bf16(acc[2 * j + 1], ah, bh[2], bh[3]);
                mma_bf16(acc[2 * j + 1], ah, bl[2], bl[3]);
                mma_bf16(acc[2 * j + 1], al, bh[2], bh[3]);
            }
        }
        __syncthreads();
    }

    // ---- epilogue ----
    float sv[2] = {0.f, 0.f}, dv[2] = {0.f, 0.f};
    const int row0 = bm + rb + g;
#pragma unroll
    for (int nt = 0; nt < 8; nt++) {
        int cb = n0 + nt * 8 + tig * 2;
        float2 bb = *(const float2*)&b[cb];
        float2 as = *(const float2*)&att[cb];
        float2 ad = *(const float2*)&att[FEAT + cb];
        float z0 = acc[nt][0] + bb.x;
        float z1 = acc[nt][1] + bb.y;
        float z2 = acc[nt][2] + bb.x;
        float z3 = acc[nt][3] + bb.y;
        *(float2*)&g_z[(size_t)row0 * FEAT + cb]       = make_float2(z0, z1);
        *(float2*)&g_z[(size_t)(row0 + 8) * FEAT + cb] = make_float2(z2, z3);
        sv[0] += z0 * as.x + z1 * as.y;
        sv[1] += z2 * as.x + z3 * as.y;
        dv[0] += z0 * ad.x + z1 * ad.y;
        dv[1] += z2 * ad.x + z3 * ad.y;
    }
#pragma unroll
    for (int h = 0; h < 2; h++) {
        sv[h] += __shfl_xor_sync(0xffffffffu, sv[h], 1);
        sv[h] += __shfl_xor_sync(0xffffffffu, sv[h], 2);
        dv[h] += __shfl_xor_sync(0xffffffffu, dv[h], 1);
        dv[h] += __shfl_xor_sync(0xffffffffu, dv[h], 2);
    }
    if (tig == 0) {
        int rl0 = rb + g;
        sdp[(nw * 64 + rl0) * 2 + 0]     = sv[0];
        sdp[(nw * 64 + rl0) * 2 + 1]     = dv[0];
        sdp[(nw * 64 + rl0 + 8) * 2 + 0] = sv[1];
        sdp[(nw * 64 + rl0 + 8) * 2 + 1] = dv[1];
    }
    __syncthreads();
    if (tid < 64) {
        float s = sdp[tid * 2]     + sdp[(64 + tid) * 2];
        float d = sdp[tid * 2 + 1] + sdp[(64 + tid) * 2 + 1];
        int row = bm + tid;
        g_s[row] = s;
        g_d[row] = d;
        unsigned int key = float_key(d);
        g_dkey[row] = ((unsigned long long)key << 32) | (unsigned int)row;
        unsigned int kmn = key, kmx = key;
#pragma unroll
        for (int off = 16; off; off >>= 1) {
            kmn = min(kmn, __shfl_xor_sync(0xffffffffu, kmn, off));
            kmx = max(kmx, __shfl_xor_sync(0xffffffffu, kmx, off));
        }
        if (lane == 0) {
            atomicMin(&g_kmin, kmn);
            atomicMax(&g_kmax, kmx);
        }
    }
}

// ---------------- 4) histogram by monotone bucket ----------------------------
__global__ void hist_kernel() {
    int i = blockIdx.x * 256 + threadIdx.x;
    unsigned int key = (unsigned int)(g_dkey[i] >> 32);
    unsigned int kmin = g_kmin;
    unsigned long long range = (unsigned long long)(g_kmax - kmin) + 1ull;
    int bin = (int)(((unsigned long long)(key - kmin) * NBUK) / range);
    g_bin[i] = bin;
    atomicAdd(&g_hist[bin], 1);
}

// ---------------- 5) exclusive scan of histogram -----------------------------
__global__ void hscan_kernel() {
    __shared__ int wsum[32];
    int t = threadIdx.x;      // 1024
    int4 h = *(const int4*)&g_hist[t * 4];
    int s = h.x + h.y + h.z + h.w;
    int lane = t & 31, wid = t >> 5;
    int sc = s;
#pragma unroll
    for (int off = 1; off < 32; off <<= 1) {
        int o = __shfl_up_sync(0xffffffffu, sc, off);
        if (lane >= off) sc += o;
    }
    if (lane == 31) wsum[wid] = sc;
    __syncthreads();
    if (wid == 0) {
        int v = wsum[lane];
#pragma unroll
        for (int off = 1; off < 32; off <<= 1) {
            int o = __shfl_up_sync(0xffffffffu, v, off);
            if (lane >= off) v += o;
        }
        wsum[lane] = v;
    }
    __syncthreads();
    int base = (wid > 0 ? wsum[wid - 1] : 0) + sc - s;
    g_hstart[t * 4 + 0] = base;
    g_hstart[t * 4 + 1] = base + h.x;
    g_hstart[t * 4 + 2] = base + h.x + h.y;
    g_hstart[t * 4 + 3] = base + h.x + h.y + h.z;
}

// ---------------- 6) place keys into bucket segments -------------------------
__global__ void place_kernel() {
    int i = blockIdx.x * 256 + threadIdx.x;
    int bin = g_bin[i];
    int pos = atomicAdd(&g_hcur[bin], 1);
    g_bkeys[g_hstart[bin] + pos] = g_dkey[i];
}

// ---------------- 7) rank within bucket + inverse perm -----------------------
__global__ void rank_kernel() {
    int i = blockIdx.x * 256 + threadIdx.x;
    int bin = g_bin[i];
    int st  = g_hstart[bin];
    int cnt = g_hist[bin];
    unsigned long long kj = g_dkey[i];
    int c = 0;
    for (int q = 0; q < cnt; q++) c += (g_bkeys[st + q] < kj) ? 1 : 0;
    int r = st + c;
    float d = g_d[i];
    g_inv[r]     = i;
    g_sortedD[r] = d;
    g_expD[r]    = expf(d);
}

// ---------------- 8) local scans per 64-row tile -----------------------------
__global__ void scanA_kernel() {
    int b    = blockIdx.x;
    int f    = threadIdx.x;   // 128
    int base = b * TR;
    __shared__ int   jidx[TR];
    __shared__ float ed[TR];
    if (f < TR) {
        jidx[f] = g_inv[base + f];
        ed[f]   = g_expD[base + f];
    }
    __syncthreads();

    float acc = 0.f;
    for (int t = 0; t < TR; t++) {
        g_S0[(size_t)(base + t) * FEAT + f] = acc;
        acc += g_z[(size_t)jidx[t] * FEAT + f];
    }
    g_T0[b * FEAT + f] = acc;

    float accS = 0.f;
    for (int t = TR - 1; t >= 0; t--) {
        accS += ed[t] * g_z[(size_t)jidx[t] * FEAT + f];
        g_SufE[(size_t)(base + t) * FEAT + f] = accS;
    }
    g_TS[b * FEAT + f] = accS;

    if (f < 32) {
        float v0 = ed[2 * f], v1 = ed[2 * f + 1];
        float seg = v0 + v1;
        float suf = seg;
#pragma unroll
        for (int off = 1; off < 32; off <<= 1) {
            float t2 = __shfl_down_sync(0xffffffffu, suf, off);
            if (f + off < 32) suf += t2;
        }
        float excl = suf - seg;
        g_c1[base + 2 * f + 1] = excl + v1;
        g_c1[base + 2 * f]     = excl + v1 + v0;
        if (f == 0) g_Tc[b] = suf;
    }
}

// ---------------- 9) scan tile totals ----------------------------------------
__global__ void scanB_kernel() {
    int f = threadIdx.x;   // 128
    float run = 0.f;
    for (int b2 = 0; b2 < NBR; b2++) {
        g_off0[b2 * FEAT + f] = run;
        run += g_T0[b2 * FEAT + f];
    }
    g_off0[NBR * FEAT + f] = run;
    g_S0[(size_t)NROW * FEAT + f] = 0.f;

    float run2 = 0.f;
    g_offS[NBR * FEAT + f] = 0.f;
    for (int b2 = NBR - 1; b2 >= 0; b2--) {
        g_offS[b2 * FEAT + f] = run2;
        run2 += g_TS[b2 * FEAT + f];
    }
    g_SufE[(size_t)NROW * FEAT + f] = 0.f;

    if (f < 32) {
        float vals[6];
        float seg = 0.f;
#pragma unroll
        for (int q = 0; q < 6; q++) { vals[q] = g_Tc[f * 6 + q]; seg += vals[q]; }
        float suf = seg;
#pragma unroll
        for (int off = 1; off < 32; off <<= 1) {
            float t2 = __shfl_down_sync(0xffffffffu, suf, off);
            if (f + off < 32) suf += t2;
        }
        float run3 = suf - seg;
#pragma unroll
        for (int q = 5; q >= 0; q--) {
            g_offc[f * 6 + q] = run3;
            run3 += vals[q];
        }
        if (f == 0) { g_offc[NBR] = 0.f; g_c1[NROW] = 0.f; }
    }
}

// ---------------- 10) combine + final row softmax ----------------------------
__global__ void combine_kernel(float* __restrict__ out) {
    int i = blockIdx.x;
    int f = threadIdx.x;   // 128

    float s = g_s[i];
    float thr = -s;
    int lo = 0, hi = NROW;
#pragma unroll 1
    while (lo < hi) {
        int mid = (lo + hi) >> 1;
        if (g_sortedD[mid] <= thr) lo = mid + 1;
        else hi = mid;
    }
    int k   = lo;
    int blk = k >> 6;

    float dmax  = g_sortedD[NROW - 1];
    float m     = fmaxf(0.f, s + dmax);
    float alpha = expf(s - m);
    float beta  = expf(-m);
    float den   = alpha * (g_offc[blk] + g_c1[k]) + beta * (float)k;

    size_t kb = (size_t)k * FEAT + f;
    size_t ob = (size_t)blk * FEAT + f;
    float num = alpha * (g_offS[ob] + g_SufE[kb]) + beta * (g_off0[ob] + g_S0[kb]);
    float z2  = num / den + g_z[(size_t)i * FEAT + f];

    __shared__ float red[4];
    float mx = z2;
    for (int off = 16; off; off >>= 1) mx = fmaxf(mx, __shfl_xor_sync(0xffffffffu, mx, off));
    if ((f & 31) == 0) red[f >> 5] = mx;
    __syncthreads();
    mx = fmaxf(fmaxf(red[0], red[1]), fmaxf(red[2], red[3]));
    float e = expf(z2 - mx);
    float sm = e;
    for (int off = 16; off; off >>= 1) sm += __shfl_xor_sync(0xffffffffu, sm, off);
    __syncthreads();
    if ((f & 31) == 0) red[f >> 5] = sm;
    __syncthreads();
    sm = red[0] + red[1] + red[2] + red[3];
    out[(size_t)i * FEAT + f] = e / sm;
}

// ---------------- launch ------------------------------------------------------
extern "C" void kernel_launch(void* const* d_in, const int* in_sizes, int n_in,
                              void* d_out, int out_size) {
    const float* x   = (const float*)d_in[0];   // [12288, 512]
    const float* v   = (const float*)d_in[1];   // [128, 512]
    const float* g   = (const float*)d_in[2];   // [128]
    const float* b   = (const float*)d_in[3];   // [128]
    const float* att = (const float*)d_in[4];   // [256]
    float* out = (float*)d_out;                 // [12288, 128]

    const int smem = (2 * 64 * SA + 2 * 128 * SA) * 2;   // 55296 bytes
    cudaFuncSetAttribute(gemm_mma_kernel, cudaFuncAttributeMaxDynamicSharedMemorySize, smem);

    scale_kernel<<<FEAT, 128>>>(v, g);
    vsplit_kernel<<<FEAT, 128>>>(v);
    gemm_mma_kernel<<<NROW / 64, 256, smem>>>(x, b, att);
    hist_kernel<<<CBLK, 256>>>();
    hscan_kernel<<<1, 1024>>>();
    place_kernel<<<CBLK, 256>>>();
    rank_kernel<<<CBLK, 256>>>();
    scanA_kernel<<<NBR, 128>>>();
    scanB_kernel<<<1, 128>>>();
    combine_kernel<<<NROW, 128>>>(out);
}

// round 7
// speedup vs baseline: 2.2803x; 1.3875x over previous
#include <cuda_runtime.h>
#include <cuda_bf16.h>
#include <math.h>
#include <stdint.h>

#define NROW 12288
#define DIM  512
#define FEAT 128
#define TR   64            // rows per scan tile
#define NBR  192           // NROW / TR
#define SA   72            // padded bf16 row stride in smem (conflict-free)
#define NBUK 4096

// ---------------- scratch (device globals; allocations forbidden) -----------
__device__ float g_scale[FEAT];
__device__ unsigned short g_vhi[FEAT * DIM];
__device__ unsigned short g_vlo[FEAT * DIM];
__device__ float g_z[NROW * FEAT];
__device__ float g_s[NROW];
__device__ float g_d[NROW];
__device__ unsigned long long g_dkey[NROW];
__device__ int   g_bin[NROW];
__device__ int   g_hist[NBUK];
__device__ int   g_hcur[NBUK];
__device__ int   g_hstart[NBUK];
__device__ unsigned long long g_bkeys[NROW];
__device__ unsigned int g_kmin, g_kmax;
__device__ int   g_inv[NROW];
__device__ float g_sortedD[NROW];
__device__ float g_expD[NROW];
__device__ float g_S0[(NROW + 1) * FEAT];
__device__ float g_SufE[(NROW + 1) * FEAT];
__device__ float g_c1[NROW + 1];
__device__ float g_T0[NBR * FEAT];
__device__ float g_TS[NBR * FEAT];
__device__ float g_Tc[NBR];
__device__ float g_off0[(NBR + 1) * FEAT];
__device__ float g_offS[(NBR + 1) * FEAT];
__device__ float g_offc[NBR + 1];
__device__ int   g_cnt1, g_gen1;   // sort-kernel barrier
__device__ int   g_cnt2, g_gen2;   // scan-kernel barrier

// ---------------- helpers -----------------------------------------------------
__device__ __forceinline__ void grid_barrier(int expected, int* cnt, int* gen) {
    __syncthreads();
    if (threadIdx.x == 0) {
        int g0 = *((volatile int*)gen);
        __threadfence();
        if (atomicAdd(cnt, 1) == expected - 1) {
            *((volatile int*)cnt) = 0;
            __threadfence();
            atomicAdd(gen, 1);
        } else {
            while (*((volatile int*)gen) == g0) { }
            __threadfence();
        }
    }
    __syncthreads();
}
__device__ __forceinline__ unsigned int float_key(float x) {
    unsigned int u = __float_as_uint(x);
    return (u & 0x80000000u) ? ~u : (u | 0x80000000u);
}
__device__ __forceinline__ uint32_t smem_u32(const void* p) {
    uint32_t a;
    asm("{ .reg .u64 t; cvta.to.shared.u64 t, %1; cvt.u32.u64 %0, t; }" : "=r"(a) : "l"(p));
    return a;
}
__device__ __forceinline__ void mma_bf16(float* c, const uint32_t* a,
                                         uint32_t b0, uint32_t b1) {
    asm volatile(
        "mma.sync.aligned.m16n8k16.row.col.f32.bf16.bf16.f32 "
        "{%0,%1,%2,%3}, {%4,%5,%6,%7}, {%8,%9}, {%0,%1,%2,%3};"
        : "+f"(c[0]), "+f"(c[1]), "+f"(c[2]), "+f"(c[3])
        : "r"(a[0]), "r"(a[1]), "r"(a[2]), "r"(a[3]), "r"(b0), "r"(b1));
}
#define LDSM4(r, addr) \
    asm volatile("ldmatrix.sync.aligned.m8n8.x4.shared.b16 {%0,%1,%2,%3}, [%4];" \
        : "=r"((r)[0]), "=r"((r)[1]), "=r"((r)[2]), "=r"((r)[3]) : "r"(addr))

// ---------------- 1) prep: scale + v split + key-range reset -----------------
__global__ void prep_kernel(const float* __restrict__ v, const float* __restrict__ g) {
    int f = blockIdx.x;
    int t = threadIdx.x;
    if (f == 0 && t == 0) { g_kmin = 0xFFFFFFFFu; g_kmax = 0u; }

    float ss = 0.f;
    for (int q = t; q < DIM; q += 128) {
        float vv = v[(size_t)f * DIM + q];
        ss += vv * vv;
    }
    __shared__ float red[4];
    __shared__ float s_sc;
    for (int off = 16; off; off >>= 1) ss += __shfl_xor_sync(0xffffffffu, ss, off);
    if ((t & 31) == 0) red[t >> 5] = ss;
    __syncthreads();
    if (t == 0) {
        float sc = g[f] / sqrtf(red[0] + red[1] + red[2] + red[3]);
        g_scale[f] = sc;
        s_sc = sc;
    }
    __syncthreads();
    float sc = s_sc;
    for (int k = t; k < DIM; k += 128) {
        float val = v[(size_t)f * DIM + k] * sc;
        __nv_bfloat16 h = __float2bfloat16(val);
        float lo = val - __bfloat162float(h);
        g_vhi[f * DIM + k] = __bfloat16_as_ushort(h);
        g_vlo[f * DIM + k] = __bfloat16_as_ushort(__float2bfloat16(lo));
    }
}

// ---------------- 2) HMMA GEMM z = x@v'^T + b, fused epilogue ----------------
__global__ void __launch_bounds__(256) gemm_mma_kernel(const float* __restrict__ x,
                                                       const float* __restrict__ b,
                                                       const float* __restrict__ att) {
    extern __shared__ unsigned short sm[];
    unsigned short* aH = sm;                       // 64*SA
    unsigned short* aL = sm + 64 * SA;
    unsigned short* bH = sm + 2 * 64 * SA;         // 128*SA
    unsigned short* bL = sm + 2 * 64 * SA + 128 * SA;
    float* sdp = (float*)sm;                       // reused after mainloop

    const int tid  = threadIdx.x;
    const int w    = tid >> 5;
    const int lane = tid & 31;
    const int g    = lane >> 2;
    const int tig  = lane & 3;
    const int mw   = w & 3;
    const int nw   = w >> 2;
    const int bm   = blockIdx.x * 64;
    const int rb   = mw * 16;
    const int n0   = nw * 64;

    const uint32_t aHs = smem_u32(aH), aLs = smem_u32(aL);
    const uint32_t bHs = smem_u32(bH), bLs = smem_u32(bL);

    const int rA = (lane & 7) + ((lane >> 3) & 1) * 8;
    const int cA = (lane >> 4) * 8;
    const uint32_t aAdH = aHs + ((rb + rA) * SA + cA) * 2;
    const uint32_t aAdL = aLs + ((rb + rA) * SA + cA) * 2;
    const int rB = (lane & 7) + (lane >> 4) * 8;
    const int cB = ((lane >> 3) & 1) * 8;
    uint32_t bAdH[4], bAdL[4];
#pragma unroll
    for (int j = 0; j < 4; j++) {
        bAdH[j] = bHs + ((n0 + j * 16 + rB) * SA + cB) * 2;
        bAdL[j] = bLs + ((n0 + j * 16 + rB) * SA + cB) * 2;
    }

    float acc[8][4];
#pragma unroll
    for (int nt = 0; nt < 8; nt++)
#pragma unroll
        for (int q = 0; q < 4; q++) acc[nt][q] = 0.f;

    for (int c = 0; c < 8; c++) {
        const int k0 = c * 64;
#pragma unroll
        for (int p = 0; p < 4; p++) {
            int li = tid + p * 256;
            int r  = li >> 4;
            int c4 = (li & 15) * 4;
            float4 xv = *(const float4*)(x + (size_t)(bm + r) * DIM + k0 + c4);
            __nv_bfloat16 h0 = __float2bfloat16(xv.x);
            __nv_bfloat16 h1 = __float2bfloat16(xv.y);
            __nv_bfloat16 h2 = __float2bfloat16(xv.z);
            __nv_bfloat16 h3 = __float2bfloat16(xv.w);
            uint2 hv, lv;
            hv.x = ((uint32_t)__bfloat16_as_ushort(h1) << 16) | __bfloat16_as_ushort(h0);
            hv.y = ((uint32_t)__bfloat16_as_ushort(h3) << 16) | __bfloat16_as_ushort(h2);
            __nv_bfloat16 l0 = __float2bfloat16(xv.x - __bfloat162float(h0));
            __nv_bfloat16 l1 = __float2bfloat16(xv.y - __bfloat162float(h1));
            __nv_bfloat16 l2 = __float2bfloat16(xv.z - __bfloat162float(h2));
            __nv_bfloat16 l3 = __float2bfloat16(xv.w - __bfloat162float(h3));
            lv.x = ((uint32_t)__bfloat16_as_ushort(l1) << 16) | __bfloat16_as_ushort(l0);
            lv.y = ((uint32_t)__bfloat16_as_ushort(l3) << 16) | __bfloat16_as_ushort(l2);
            *(uint2*)&aH[r * SA + c4] = hv;
            *(uint2*)&aL[r * SA + c4] = lv;
        }
#pragma unroll
        for (int p = 0; p < 4; p++) {
            int li = tid + p * 256;
            int r  = li >> 3;
            int u  = li & 7;
            size_t gv = (size_t)r * DIM + k0 + u * 8;
            *(uint4*)&bH[r * SA + u * 8] = *(const uint4*)&g_vhi[gv];
            *(uint4*)&bL[r * SA + u * 8] = *(const uint4*)&g_vlo[gv];
        }
        __syncthreads();

#pragma unroll
        for (int kt = 0; kt < 4; kt++) {
            uint32_t ah[4], al[4];
            LDSM4(ah, aAdH + kt * 32);
            LDSM4(al, aAdL + kt * 32);
#pragma unroll
            for (int j = 0; j < 4; j++) {
                uint32_t bh[4], bl[4];
                LDSM4(bh, bAdH[j] + kt * 32);
                LDSM4(bl, bAdL[j] + kt * 32);
                mma_bf16(acc[2 * j],     ah, bh[0], bh[1]);
                mma_bf16(acc[2 * j],     ah, bl[0], bl[1]);
                mma_bf16(acc[2 * j],     al, bh[0], bh[1]);
                mma_bf16(acc[2 * j + 1], ah, bh[2], bh[3]);
                mma_bf16(acc[2 * j + 1], ah, bl[2], bl[3]);
                mma_bf16(acc[2 * j + 1], al, bh[2], bh[3]);
            }
        }
        __syncthreads();
    }

    // ---- epilogue ----
    float sv[2] = {0.f, 0.f}, dv[2] = {0.f, 0.f};
    const int row0 = bm + rb + g;
#pragma unroll
    for (int nt = 0; nt < 8; nt++) {
        int cb = n0 + nt * 8 + tig * 2;
        float2 bb = *(const float2*)&b[cb];
        float2 as = *(const float2*)&att[cb];
        float2 ad = *(const float2*)&att[FEAT + cb];
        float z0 = acc[nt][0] + bb.x;
        float z1 = acc[nt][1] + bb.y;
        float z2 = acc[nt][2] + bb.x;
        float z3 = acc[nt][3] + bb.y;
        *(float2*)&g_z[(size_t)row0 * FEAT + cb]       = make_float2(z0, z1);
        *(float2*)&g_z[(size_t)(row0 + 8) * FEAT + cb] = make_float2(z2, z3);
        sv[0] += z0 * as.x + z1 * as.y;
        sv[1] += z2 * as.x + z3 * as.y;
        dv[0] += z0 * ad.x + z1 * ad.y;
        dv[1] += z2 * ad.x + z3 * ad.y;
    }
#pragma unroll
    for (int h = 0; h < 2; h++) {
        sv[h] += __shfl_xor_sync(0xffffffffu, sv[h], 1);
        sv[h] += __shfl_xor_sync(0xffffffffu, sv[h], 2);
        dv[h] += __shfl_xor_sync(0xffffffffu, dv[h], 1);
        dv[h] += __shfl_xor_sync(0xffffffffu, dv[h], 2);
    }
    if (tig == 0) {
        int rl0 = rb + g;
        sdp[(nw * 64 + rl0) * 2 + 0]     = sv[0];
        sdp[(nw * 64 + rl0) * 2 + 1]     = dv[0];
        sdp[(nw * 64 + rl0 + 8) * 2 + 0] = sv[1];
        sdp[(nw * 64 + rl0 + 8) * 2 + 1] = dv[1];
    }
    __syncthreads();
    if (tid < 64) {
        float s = sdp[tid * 2]     + sdp[(64 + tid) * 2];
        float d = sdp[tid * 2 + 1] + sdp[(64 + tid) * 2 + 1];
        int row = bm + tid;
        g_s[row] = s;
        g_d[row] = d;
        unsigned int key = float_key(d);
        g_dkey[row] = ((unsigned long long)key << 32) | (unsigned int)row;
        unsigned int kmn = key, kmx = key;
#pragma unroll
        for (int off = 16; off; off >>= 1) {
            kmn = min(kmn, __shfl_xor_sync(0xffffffffu, kmn, off));
            kmx = max(kmx, __shfl_xor_sync(0xffffffffu, kmx, off));
        }
        if (lane == 0) {
            atomicMin(&g_kmin, kmn);
            atomicMax(&g_kmax, kmx);
        }
    }
}

// ---------------- 3) fused sort: hist -> scan -> place -> rank ---------------
// 48 co-resident blocks x 256 threads, grid barriers between phases.
__global__ void __launch_bounds__(256) sort_kernel() {
    const int nb  = 48;
    const int tid = threadIdx.x;
    const int bid = blockIdx.x;
    const int i   = bid * 256 + tid;

    // phase 0: zero hist / hcur
    for (int q = i; q < NBUK; q += nb * 256) { g_hist[q] = 0; g_hcur[q] = 0; }
    grid_barrier(nb, &g_cnt1, &g_gen1);

    // phase 1: histogram
    unsigned long long kj = g_dkey[i];
    unsigned int key  = (unsigned int)(kj >> 32);
    unsigned int kmin = g_kmin;
    unsigned long long range = (unsigned long long)(g_kmax - kmin) + 1ull;
    int bin = (int)(((unsigned long long)(key - kmin) * NBUK) / range);
    g_bin[i] = bin;
    atomicAdd(&g_hist[bin], 1);
    grid_barrier(nb, &g_cnt1, &g_gen1);

    // phase 2: exclusive scan of 4096 bins (block 0)
    if (bid == 0) {
        __shared__ int ws[8];
        int base = tid * 16;
        int loc[16];
        int s = 0;
#pragma unroll
        for (int q = 0; q < 16; q++) { loc[q] = g_hist[base + q]; s += loc[q]; }
        int lane = tid & 31, wid = tid >> 5;
        int sc = s;
#pragma unroll
        for (int off = 1; off < 32; off <<= 1) {
            int o = __shfl_up_sync(0xffffffffu, sc, off);
            if (lane >= off) sc += o;
        }
        if (lane == 31) ws[wid] = sc;
        __syncthreads();
        if (tid == 0) {
            int run = 0;
#pragma unroll
            for (int q = 0; q < 8; q++) { int t2 = ws[q]; ws[q] = run; run += t2; }
        }
        __syncthreads();
        int run = ws[wid] + sc - s;
#pragma unroll
        for (int q = 0; q < 16; q++) { g_hstart[base + q] = run; run += loc[q]; }
    }
    grid_barrier(nb, &g_cnt1, &g_gen1);

    // phase 3: place
    int pos = atomicAdd(&g_hcur[bin], 1);
    g_bkeys[g_hstart[bin] + pos] = kj;
    grid_barrier(nb, &g_cnt1, &g_gen1);

    // phase 4: rank + inverse perm
    int st  = g_hstart[bin];
    int cnt = g_hist[bin];
    int c = 0;
    for (int q = 0; q < cnt; q++) c += (g_bkeys[st + q] < kj) ? 1 : 0;
    int r = st + c;
    float d = g_d[i];
    g_inv[r]     = i;
    g_sortedD[r] = d;
    g_expD[r]    = expf(d);
}

// ---------------- 4) fused scans: local tiles + tile totals ------------------
// 192 co-resident blocks x 256 threads; warps 0-3 prefix, warps 4-7 suffix.
__global__ void __launch_bounds__(256) scanAB_kernel() {
    int b    = blockIdx.x;
    int tid  = threadIdx.x;
    int base = b * TR;
    __shared__ int   jidx[TR];
    __shared__ float ed[TR];
    if (tid < TR) {
        jidx[tid] = g_inv[base + tid];
        ed[tid]   = g_expD[base + tid];
    }
    __syncthreads();

    if (tid < 128) {
        int f = tid;
        float acc = 0.f;
        for (int t = 0; t < TR; t++) {
            g_S0[(size_t)(base + t) * FEAT + f] = acc;
            acc += g_z[(size_t)jidx[t] * FEAT + f];
        }
        g_T0[b * FEAT + f] = acc;

        if (f < 32) {
            float v0 = ed[2 * f], v1 = ed[2 * f + 1];
            float seg = v0 + v1;
            float suf = seg;
#pragma unroll
            for (int off = 1; off < 32; off <<= 1) {
                float t2 = __shfl_down_sync(0xffffffffu, suf, off);
                if (f + off < 32) suf += t2;
            }
            float excl = suf - seg;
            g_c1[base + 2 * f + 1] = excl + v1;
            g_c1[base + 2 * f]     = excl + v1 + v0;
            if (f == 0) g_Tc[b] = suf;
        }
    } else {
        int f = tid - 128;
        float accS = 0.f;
        for (int t = TR - 1; t >= 0; t--) {
            accS += ed[t] * g_z[(size_t)jidx[t] * FEAT + f];
            g_SufE[(size_t)(base + t) * FEAT + f] = accS;
        }
        g_TS[b * FEAT + f] = accS;
    }

    grid_barrier(NBR, &g_cnt2, &g_gen2);

    if (b == 0) {
        if (tid < 128) {
            int f = tid;
            float run = 0.f;
            for (int b2 = 0; b2 < NBR; b2++) {
                g_off0[b2 * FEAT + f] = run;
                run += g_T0[b2 * FEAT + f];
            }
            g_off0[NBR * FEAT + f] = run;
            g_S0[(size_t)NROW * FEAT + f] = 0.f;

            if (f < 32) {
                float vals[6];
                float seg = 0.f;
#pragma unroll
                for (int q = 0; q < 6; q++) { vals[q] = g_Tc[f * 6 + q]; seg += vals[q]; }
                float suf = seg;
#pragma unroll
                for (int off = 1; off < 32; off <<= 1) {
                    float t2 = __shfl_down_sync(0xffffffffu, suf, off);
                    if (f + off < 32) suf += t2;
                }
                float run3 = suf - seg;
#pragma unroll
                for (int q = 5; q >= 0; q--) {
                    g_offc[f * 6 + q] = run3;
                    run3 += vals[q];
                }
                if (f == 0) { g_offc[NBR] = 0.f; g_c1[NROW] = 0.f; }
            }
        } else {
            int f = tid - 128;
            float run2 = 0.f;
            g_offS[NBR * FEAT + f] = 0.f;
            for (int b2 = NBR - 1; b2 >= 0; b2--) {
                g_offS[b2 * FEAT + f] = run2;
                run2 += g_TS[b2 * FEAT + f];
            }
            g_SufE[(size_t)NROW * FEAT + f] = 0.f;
        }
    }
}

// ---------------- 5) combine: warp per row, shuffle-only softmax -------------
__global__ void __launch_bounds__(128) combine_kernel(float* __restrict__ out) {
    int w    = threadIdx.x >> 5;
    int lane = threadIdx.x & 31;
    int i    = blockIdx.x * 4 + w;
    int f4   = lane * 4;

    float s = g_s[i];
    float thr = -s;
    int lo = 0, hi = NROW;
#pragma unroll 1
    while (lo < hi) {
        int mid = (lo + hi) >> 1;
        if (g_sortedD[mid] <= thr) lo = mid + 1;
        else hi = mid;
    }
    int k   = lo;
    int blk = k >> 6;

    float dmax  = g_sortedD[NROW - 1];
    float m     = fmaxf(0.f, s + dmax);
    float alpha = expf(s - m);
    float beta  = expf(-m);
    float den   = alpha * (g_offc[blk] + g_c1[k]) + beta * (float)k;
    float rden  = 1.f / den;

    float4 SufE = *(const float4*)&g_SufE[(size_t)k * FEAT + f4];
    float4 S0   = *(const float4*)&g_S0[(size_t)k * FEAT + f4];
    float4 offS = *(const float4*)&g_offS[(size_t)blk * FEAT + f4];
    float4 off0 = *(const float4*)&g_off0[(size_t)blk * FEAT + f4];
    float4 zv   = *(const float4*)&g_z[(size_t)i * FEAT + f4];

    float z2[4];
    z2[0] = (alpha * (offS.x + SufE.x) + beta * (off0.x + S0.x)) * rden + zv.x;
    z2[1] = (alpha * (offS.y + SufE.y) + beta * (off0.y + S0.y)) * rden + zv.y;
    z2[2] = (alpha * (offS.z + SufE.z) + beta * (off0.z + S0.z)) * rden + zv.z;
    z2[3] = (alpha * (offS.w + SufE.w) + beta * (off0.w + S0.w)) * rden + zv.w;

    float mx = fmaxf(fmaxf(z2[0], z2[1]), fmaxf(z2[2], z2[3]));
#pragma unroll
    for (int off = 16; off; off >>= 1) mx = fmaxf(mx, __shfl_xor_sync(0xffffffffu, mx, off));
    float e[4];
    float sm = 0.f;
#pragma unroll
    for (int q = 0; q < 4; q++) { e[q] = expf(z2[q] - mx); sm += e[q]; }
#pragma unroll
    for (int off = 16; off; off >>= 1) sm += __shfl_xor_sync(0xffffffffu, sm, off);
    float rs = 1.f / sm;
    float4 o = {e[0] * rs, e[1] * rs, e[2] * rs, e[3] * rs};
    *(float4*)&out[(size_t)i * FEAT + f4] = o;
}

// ---------------- launch ------------------------------------------------------
extern "C" void kernel_launch(void* const* d_in, const int* in_sizes, int n_in,
                              void* d_out, int out_size) {
    const float* x   = (const float*)d_in[0];   // [12288, 512]
    const float* v   = (const float*)d_in[1];   // [128, 512]
    const float* g   = (const float*)d_in[2];   // [128]
    const float* b   = (const float*)d_in[3];   // [128]
    const float* att = (const float*)d_in[4];   // [256]
    float* out = (float*)d_out;                 // [12288, 128]

    const int smem = (2 * 64 * SA + 2 * 128 * SA) * 2;   // 55296 bytes
    cudaFuncSetAttribute(gemm_mma_kernel, cudaFuncAttributeMaxDynamicSharedMemorySize, smem);

    prep_kernel<<<FEAT, 128>>>(v, g);
    gemm_mma_kernel<<<NROW / 64, 256, smem>>>(x, b, att);
    sort_kernel<<<48, 256>>>();
    scanAB_kernel<<<NBR, 256>>>();
    combine_kernel<<<NROW / 4, 128>>>(out);
}

// round 8
// speedup vs baseline: 3.7212x; 1.6319x over previous
#include <cuda_runtime.h>
#include <cuda_bf16.h>
#include <math.h>
#include <stdint.h>

#define NROW 12288
#define DIM  512
#define FEAT 128
#define TR   64            // rows per scan tile
#define NBR  192           // NROW / TR
#define SA   72            // padded bf16 row stride in smem (conflict-free)
#define NBUK 4096

// ---------------- scratch (device globals; allocations forbidden) -----------
__device__ float g_scale[FEAT];
__device__ unsigned short g_vhi[FEAT * DIM];
__device__ unsigned short g_vlo[FEAT * DIM];
__device__ float g_z[NROW * FEAT];
__device__ float g_s[NROW];
__device__ float g_d[NROW];
__device__ unsigned long long g_dkey[NROW];
__device__ int   g_bin[NROW];
__device__ int   g_hist[NBUK];
__device__ int   g_hcur[NBUK];
__device__ int   g_hstart[NBUK];
__device__ unsigned long long g_bkeys[NROW];
__device__ unsigned int g_kmin, g_kmax;
__device__ int   g_inv[NROW];
__device__ float g_sortedD[NROW];
__device__ float g_expD[NROW];
__device__ float g_S0[(NROW + 1) * FEAT];
__device__ float g_SufE[(NROW + 1) * FEAT];
__device__ float g_c1[NROW + 1];
__device__ float g_T0[NBR * FEAT];
__device__ float g_TS[NBR * FEAT];
__device__ float g_Tc[NBR];
__device__ float g_off0[(NBR + 1) * FEAT];
__device__ float g_offS[(NBR + 1) * FEAT];
__device__ float g_offc[NBR + 1];
__device__ int   g_cnt1, g_gen1;   // sort-kernel barrier
__device__ int   g_cnt2, g_gen2;   // scan-kernel barrier

// ---------------- helpers -----------------------------------------------------
__device__ __forceinline__ void grid_barrier(int expected, int* cnt, int* gen) {
    __syncthreads();
    if (threadIdx.x == 0) {
        int g0 = *((volatile int*)gen);
        __threadfence();
        if (atomicAdd(cnt, 1) == expected - 1) {
            *((volatile int*)cnt) = 0;
            __threadfence();
            atomicAdd(gen, 1);
        } else {
            while (*((volatile int*)gen) == g0) { __nanosleep(64); }
            __threadfence();
        }
    }
    __syncthreads();
}
__device__ __forceinline__ unsigned int float_key(float x) {
    unsigned int u = __float_as_uint(x);
    return (u & 0x80000000u) ? ~u : (u | 0x80000000u);
}
__device__ __forceinline__ uint32_t smem_u32(const void* p) {
    uint32_t a;
    asm("{ .reg .u64 t; cvta.to.shared.u64 t, %1; cvt.u32.u64 %0, t; }" : "=r"(a) : "l"(p));
    return a;
}
__device__ __forceinline__ void mma_bf16(float* c, const uint32_t* a,
                                         uint32_t b0, uint32_t b1) {
    asm volatile(
        "mma.sync.aligned.m16n8k16.row.col.f32.bf16.bf16.f32 "
        "{%0,%1,%2,%3}, {%4,%5,%6,%7}, {%8,%9}, {%0,%1,%2,%3};"
        : "+f"(c[0]), "+f"(c[1]), "+f"(c[2]), "+f"(c[3])
        : "r"(a[0]), "r"(a[1]), "r"(a[2]), "r"(a[3]), "r"(b0), "r"(b1));
}
#define LDSM4(r, addr) \
    asm volatile("ldmatrix.sync.aligned.m8n8.x4.shared.b16 {%0,%1,%2,%3}, [%4];" \
        : "=r"((r)[0]), "=r"((r)[1]), "=r"((r)[2]), "=r"((r)[3]) : "r"(addr))

// ---------------- 1) prep: scale + v split + key-range reset -----------------
__global__ void prep_kernel(const float* __restrict__ v, const float* __restrict__ g) {
    int f = blockIdx.x;
    int t = threadIdx.x;
    if (f == 0 && t == 0) { g_kmin = 0xFFFFFFFFu; g_kmax = 0u; }

    float ss = 0.f;
    for (int q = t; q < DIM; q += 128) {
        float vv = v[(size_t)f * DIM + q];
        ss += vv * vv;
    }
    __shared__ float red[4];
    __shared__ float s_sc;
    for (int off = 16; off; off >>= 1) ss += __shfl_xor_sync(0xffffffffu, ss, off);
    if ((t & 31) == 0) red[t >> 5] = ss;
    __syncthreads();
    if (t == 0) {
        float sc = g[f] / sqrtf(red[0] + red[1] + red[2] + red[3]);
        g_scale[f] = sc;
        s_sc = sc;
    }
    __syncthreads();
    float sc = s_sc;
    for (int k = t; k < DIM; k += 128) {
        float val = v[(size_t)f * DIM + k] * sc;
        __nv_bfloat16 h = __float2bfloat16(val);
        float lo = val - __bfloat162float(h);
        g_vhi[f * DIM + k] = __bfloat16_as_ushort(h);
        g_vlo[f * DIM + k] = __bfloat16_as_ushort(__float2bfloat16(lo));
    }
}

// ---------------- 2) HMMA GEMM z = x@v'^T + b, fused epilogue ----------------
__global__ void __launch_bounds__(256) gemm_mma_kernel(const float* __restrict__ x,
                                                       const float* __restrict__ b,
                                                       const float* __restrict__ att) {
    extern __shared__ unsigned short sm[];
    unsigned short* aH = sm;                       // 64*SA
    unsigned short* aL = sm + 64 * SA;
    unsigned short* bH = sm + 2 * 64 * SA;         // 128*SA
    unsigned short* bL = sm + 2 * 64 * SA + 128 * SA;
    float* sdp = (float*)sm;                       // reused after mainloop

    const int tid  = threadIdx.x;
    const int w    = tid >> 5;
    const int lane = tid & 31;
    const int g    = lane >> 2;
    const int tig  = lane & 3;
    const int mw   = w & 3;
    const int nw   = w >> 2;
    const int bm   = blockIdx.x * 64;
    const int rb   = mw * 16;
    const int n0   = nw * 64;

    const uint32_t aHs = smem_u32(aH), aLs = smem_u32(aL);
    const uint32_t bHs = smem_u32(bH), bLs = smem_u32(bL);

    const int rA = (lane & 7) + ((lane >> 3) & 1) * 8;
    const int cA = (lane >> 4) * 8;
    const uint32_t aAdH = aHs + ((rb + rA) * SA + cA) * 2;
    const uint32_t aAdL = aLs + ((rb + rA) * SA + cA) * 2;
    const int rB = (lane & 7) + (lane >> 4) * 8;
    const int cB = ((lane >> 3) & 1) * 8;
    uint32_t bAdH[4], bAdL[4];
#pragma unroll
    for (int j = 0; j < 4; j++) {
        bAdH[j] = bHs + ((n0 + j * 16 + rB) * SA + cB) * 2;
        bAdL[j] = bLs + ((n0 + j * 16 + rB) * SA + cB) * 2;
    }

    float acc[8][4];
#pragma unroll
    for (int nt = 0; nt < 8; nt++)
#pragma unroll
        for (int q = 0; q < 4; q++) acc[nt][q] = 0.f;

    for (int c = 0; c < 8; c++) {
        const int k0 = c * 64;
#pragma unroll
        for (int p = 0; p < 4; p++) {
            int li = tid + p * 256;
            int r  = li >> 4;
            int c4 = (li & 15) * 4;
            float4 xv = *(const float4*)(x + (size_t)(bm + r) * DIM + k0 + c4);
            __nv_bfloat16 h0 = __float2bfloat16(xv.x);
            __nv_bfloat16 h1 = __float2bfloat16(xv.y);
            __nv_bfloat16 h2 = __float2bfloat16(xv.z);
            __nv_bfloat16 h3 = __float2bfloat16(xv.w);
            uint2 hv, lv;
            hv.x = ((uint32_t)__bfloat16_as_ushort(h1) << 16) | __bfloat16_as_ushort(h0);
            hv.y = ((uint32_t)__bfloat16_as_ushort(h3) << 16) | __bfloat16_as_ushort(h2);
            __nv_bfloat16 l0 = __float2bfloat16(xv.x - __bfloat162float(h0));
            __nv_bfloat16 l1 = __float2bfloat16(xv.y - __bfloat162float(h1));
            __nv_bfloat16 l2 = __float2bfloat16(xv.z - __bfloat162float(h2));
            __nv_bfloat16 l3 = __float2bfloat16(xv.w - __bfloat162float(h3));
            lv.x = ((uint32_t)__bfloat16_as_ushort(l1) << 16) | __bfloat16_as_ushort(l0);
            lv.y = ((uint32_t)__bfloat16_as_ushort(l3) << 16) | __bfloat16_as_ushort(l2);
            *(uint2*)&aH[r * SA + c4] = hv;
            *(uint2*)&aL[r * SA + c4] = lv;
        }
#pragma unroll
        for (int p = 0; p < 4; p++) {
            int li = tid + p * 256;
            int r  = li >> 3;
            int u  = li & 7;
            size_t gv = (size_t)r * DIM + k0 + u * 8;
            *(uint4*)&bH[r * SA + u * 8] = *(const uint4*)&g_vhi[gv];
            *(uint4*)&bL[r * SA + u * 8] = *(const uint4*)&g_vlo[gv];
        }
        __syncthreads();

#pragma unroll
        for (int kt = 0; kt < 4; kt++) {
            uint32_t ah[4], al[4];
            LDSM4(ah, aAdH + kt * 32);
            LDSM4(al, aAdL + kt * 32);
#pragma unroll
            for (int j = 0; j < 4; j++) {
                uint32_t bh[4], bl[4];
                LDSM4(bh, bAdH[j] + kt * 32);
                LDSM4(bl, bAdL[j] + kt * 32);
                mma_bf16(acc[2 * j],     ah, bh[0], bh[1]);
                mma_bf16(acc[2 * j],     ah, bl[0], bl[1]);
                mma_bf16(acc[2 * j],     al, bh[0], bh[1]);
                mma_bf16(acc[2 * j + 1], ah, bh[2], bh[3]);
                mma_bf16(acc[2 * j + 1], ah, bl[2], bl[3]);
                mma_bf16(acc[2 * j + 1], al, bh[2], bh[3]);
            }
        }
        __syncthreads();
    }

    // ---- epilogue ----
    float sv[2] = {0.f, 0.f}, dv[2] = {0.f, 0.f};
    const int row0 = bm + rb + g;
#pragma unroll
    for (int nt = 0; nt < 8; nt++) {
        int cb = n0 + nt * 8 + tig * 2;
        float2 bb = *(const float2*)&b[cb];
        float2 as = *(const float2*)&att[cb];
        float2 ad = *(const float2*)&att[FEAT + cb];
        float z0 = acc[nt][0] + bb.x;
        float z1 = acc[nt][1] + bb.y;
        float z2 = acc[nt][2] + bb.x;
        float z3 = acc[nt][3] + bb.y;
        *(float2*)&g_z[(size_t)row0 * FEAT + cb]       = make_float2(z0, z1);
        *(float2*)&g_z[(size_t)(row0 + 8) * FEAT + cb] = make_float2(z2, z3);
        sv[0] += z0 * as.x + z1 * as.y;
        sv[1] += z2 * as.x + z3 * as.y;
        dv[0] += z0 * ad.x + z1 * ad.y;
        dv[1] += z2 * ad.x + z3 * ad.y;
    }
#pragma unroll
    for (int h = 0; h < 2; h++) {
        sv[h] += __shfl_xor_sync(0xffffffffu, sv[h], 1);
        sv[h] += __shfl_xor_sync(0xffffffffu, sv[h], 2);
        dv[h] += __shfl_xor_sync(0xffffffffu, dv[h], 1);
        dv[h] += __shfl_xor_sync(0xffffffffu, dv[h], 2);
    }
    if (tig == 0) {
        int rl0 = rb + g;
        sdp[(nw * 64 + rl0) * 2 + 0]     = sv[0];
        sdp[(nw * 64 + rl0) * 2 + 1]     = dv[0];
        sdp[(nw * 64 + rl0 + 8) * 2 + 0] = sv[1];
        sdp[(nw * 64 + rl0 + 8) * 2 + 1] = dv[1];
    }
    __syncthreads();
    if (tid < 64) {
        float s = sdp[tid * 2]     + sdp[(64 + tid) * 2];
        float d = sdp[tid * 2 + 1] + sdp[(64 + tid) * 2 + 1];
        int row = bm + tid;
        g_s[row] = s;
        g_d[row] = d;
        unsigned int key = float_key(d);
        g_dkey[row] = ((unsigned long long)key << 32) | (unsigned int)row;
        unsigned int kmn = key, kmx = key;
#pragma unroll
        for (int off = 16; off; off >>= 1) {
            kmn = min(kmn, __shfl_xor_sync(0xffffffffu, kmn, off));
            kmx = max(kmx, __shfl_xor_sync(0xffffffffu, kmx, off));
        }
        if (lane == 0) {
            atomicMin(&g_kmin, kmn);
            atomicMax(&g_kmax, kmx);
        }
    }
}

// ---------------- 3) fused sort: hist -> scan -> place -> rank ---------------
__global__ void __launch_bounds__(256) sort_kernel() {
    const int nb  = 48;
    const int tid = threadIdx.x;
    const int bid = blockIdx.x;
    const int i   = bid * 256 + tid;

    for (int q = i; q < NBUK; q += nb * 256) { g_hist[q] = 0; g_hcur[q] = 0; }
    grid_barrier(nb, &g_cnt1, &g_gen1);

    unsigned long long kj = g_dkey[i];
    unsigned int key  = (unsigned int)(kj >> 32);
    unsigned int kmin = g_kmin;
    unsigned long long range = (unsigned long long)(g_kmax - kmin) + 1ull;
    int bin = (int)(((unsigned long long)(key - kmin) * NBUK) / range);
    g_bin[i] = bin;
    atomicAdd(&g_hist[bin], 1);
    grid_barrier(nb, &g_cnt1, &g_gen1);

    if (bid == 0) {
        __shared__ int ws[8];
        int base = tid * 16;
        int loc[16];
        int s = 0;
#pragma unroll
        for (int q = 0; q < 16; q++) { loc[q] = g_hist[base + q]; s += loc[q]; }
        int lane = tid & 31, wid = tid >> 5;
        int sc = s;
#pragma unroll
        for (int off = 1; off < 32; off <<= 1) {
            int o = __shfl_up_sync(0xffffffffu, sc, off);
            if (lane >= off) sc += o;
        }
        if (lane == 31) ws[wid] = sc;
        __syncthreads();
        if (tid == 0) {
            int run = 0;
#pragma unroll
            for (int q = 0; q < 8; q++) { int t2 = ws[q]; ws[q] = run; run += t2; }
        }
        __syncthreads();
        int run = ws[wid] + sc - s;
#pragma unroll
        for (int q = 0; q < 16; q++) { g_hstart[base + q] = run; run += loc[q]; }
    }
    grid_barrier(nb, &g_cnt1, &g_gen1);

    int pos = atomicAdd(&g_hcur[bin], 1);
    g_bkeys[g_hstart[bin] + pos] = kj;
    grid_barrier(nb, &g_cnt1, &g_gen1);

    int st  = g_hstart[bin];
    int cnt = g_hist[bin];
    int c = 0;
    for (int q = 0; q < cnt; q++) c += (g_bkeys[st + q] < kj) ? 1 : 0;
    int r = st + c;
    float d = g_d[i];
    g_inv[r]     = i;
    g_sortedD[r] = d;
    g_expD[r]    = expf(d);
}

// ---------------- 4) fused scans: MLP-batched local + parallel totals --------
__global__ void __launch_bounds__(256) scanAB_kernel() {
    int b    = blockIdx.x;
    int tid  = threadIdx.x;
    int base = b * TR;
    __shared__ int   jidx[TR];
    __shared__ float ed[TR];
    if (tid < TR) {
        jidx[tid] = g_inv[base + tid];
        ed[tid]   = g_expD[base + tid];
    }
    __syncthreads();

    if (tid < 128) {
        int f = tid;
        float acc = 0.f;
#pragma unroll
        for (int bt = 0; bt < 4; bt++) {
            float vals[16];
#pragma unroll
            for (int q = 0; q < 16; q++)
                vals[q] = g_z[(size_t)jidx[bt * 16 + q] * FEAT + f];
#pragma unroll
            for (int q = 0; q < 16; q++) {
                g_S0[(size_t)(base + bt * 16 + q) * FEAT + f] = acc;
                acc += vals[q];
            }
        }
        g_T0[b * FEAT + f] = acc;

        if (f < 32) {
            float v0 = ed[2 * f], v1 = ed[2 * f + 1];
            float seg = v0 + v1;
            float suf = seg;
#pragma unroll
            for (int off = 1; off < 32; off <<= 1) {
                float t2 = __shfl_down_sync(0xffffffffu, suf, off);
                if (f + off < 32) suf += t2;
            }
            float excl = suf - seg;
            g_c1[base + 2 * f + 1] = excl + v1;
            g_c1[base + 2 * f]     = excl + v1 + v0;
            if (f == 0) g_Tc[b] = suf;
        }
    } else {
        int f = tid - 128;
        float accS = 0.f;
#pragma unroll
        for (int bt = 3; bt >= 0; bt--) {
            float vals[16];
#pragma unroll
            for (int q = 0; q < 16; q++)
                vals[q] = ed[bt * 16 + q] * g_z[(size_t)jidx[bt * 16 + q] * FEAT + f];
#pragma unroll
            for (int q = 15; q >= 0; q--) {
                accS += vals[q];
                g_SufE[(size_t)(base + bt * 16 + q) * FEAT + f] = accS;
            }
        }
        g_TS[b * FEAT + f] = accS;
    }

    grid_barrier(NBR, &g_cnt2, &g_gen2);

    // ---- phase 2: parallel scan of tile totals (block f handles feature f) --
    if (b < 128) {
        int f = b;
        bool act = tid < NBR;
        float v0 = act ? g_T0[tid * FEAT + f] : 0.f;
        float vS = act ? g_TS[tid * FEAT + f] : 0.f;
        float i0 = v0, iS = vS;
        int lane = tid & 31, wid = tid >> 5;
#pragma unroll
        for (int off = 1; off < 32; off <<= 1) {
            float a0 = __shfl_up_sync(0xffffffffu, i0, off);
            float aS = __shfl_up_sync(0xffffffffu, iS, off);
            if (lane >= off) { i0 += a0; iS += aS; }
        }
        __shared__ float w0[8], wS[8];
        __shared__ float tot0s, totSs;
        if (lane == 31) { w0[wid] = i0; wS[wid] = iS; }
        __syncthreads();
        if (tid == 0) {
            float r0 = 0.f, rS = 0.f;
#pragma unroll
            for (int q = 0; q < 8; q++) {
                float t0 = w0[q], tS = wS[q];
                w0[q] = r0; wS[q] = rS;
                r0 += t0; rS += tS;
            }
            tot0s = r0; totSs = rS;
        }
        __syncthreads();
        i0 += w0[wid];
        iS += wS[wid];
        if (act) {
            g_off0[tid * FEAT + f] = i0 - v0;        // exclusive prefix
            g_offS[tid * FEAT + f] = totSs - iS;     // suffix over tiles > tid
        }
        if (tid == 0) {
            g_off0[NBR * FEAT + f] = tot0s;
            g_offS[NBR * FEAT + f] = 0.f;
            g_S0[(size_t)NROW * FEAT + f]   = 0.f;
            g_SufE[(size_t)NROW * FEAT + f] = 0.f;
        }
    } else if (b == 128) {
        bool act = tid < NBR;
        float vc = act ? g_Tc[tid] : 0.f;
        float ic = vc;
        int lane = tid & 31, wid = tid >> 5;
#pragma unroll
        for (int off = 1; off < 32; off <<= 1) {
            float a = __shfl_up_sync(0xffffffffu, ic, off);
            if (lane >= off) ic += a;
        }
        __shared__ float wc[8];
        __shared__ float totc;
        if (lane == 31) wc[wid] = ic;
        __syncthreads();
        if (tid == 0) {
            float r = 0.f;
#pragma unroll
            for (int q = 0; q < 8; q++) { float t2 = wc[q]; wc[q] = r; r += t2; }
            totc = r;
        }
        __syncthreads();
        ic += wc[wid];
        if (act) g_offc[tid] = totc - ic;
        if (tid == 0) { g_offc[NBR] = 0.f; g_c1[NROW] = 0.f; }
    }
}

// ---------------- 5) combine: warp per row, shuffle-only softmax -------------
__global__ void __launch_bounds__(128) combine_kernel(float* __restrict__ out) {
    int w    = threadIdx.x >> 5;
    int lane = threadIdx.x & 31;
    int i    = blockIdx.x * 4 + w;
    int f4   = lane * 4;

    float s = g_s[i];
    float thr = -s;
    int lo = 0, hi = NROW;
#pragma unroll 1
    while (lo < hi) {
        int mid = (lo + hi) >> 1;
        if (g_sortedD[mid] <= thr) lo = mid + 1;
        else hi = mid;
    }
    int k   = lo;
    int blk = k >> 6;

    float dmax  = g_sortedD[NROW - 1];
    float m     = fmaxf(0.f, s + dmax);
    float alpha = expf(s - m);
    float beta  = expf(-m);
    float den   = alpha * (g_offc[blk] + g_c1[k]) + beta * (float)k;
    float rden  = 1.f / den;

    float4 SufE = *(const float4*)&g_SufE[(size_t)k * FEAT + f4];
    float4 S0   = *(const float4*)&g_S0[(size_t)k * FEAT + f4];
    float4 offS = *(const float4*)&g_offS[(size_t)blk * FEAT + f4];
    float4 off0 = *(const float4*)&g_off0[(size_t)blk * FEAT + f4];
    float4 zv   = *(const float4*)&g_z[(size_t)i * FEAT + f4];

    float z2[4];
    z2[0] = (alpha * (offS.x + SufE.x) + beta * (off0.x + S0.x)) * rden + zv.x;
    z2[1] = (alpha * (offS.y + SufE.y) + beta * (off0.y + S0.y)) * rden + zv.y;
    z2[2] = (alpha * (offS.z + SufE.z) + beta * (off0.z + S0.z)) * rden + zv.z;
    z2[3] = (alpha * (offS.w + SufE.w) + beta * (off0.w + S0.w)) * rden + zv.w;

    float mx = fmaxf(fmaxf(z2[0], z2[1]), fmaxf(z2[2], z2[3]));
#pragma unroll
    for (int off = 16; off; off >>= 1) mx = fmaxf(mx, __shfl_xor_sync(0xffffffffu, mx, off));
    float e[4];
    float sm = 0.f;
#pragma unroll
    for (int q = 0; q < 4; q++) { e[q] = expf(z2[q] - mx); sm += e[q]; }
#pragma unroll
    for (int off = 16; off; off >>= 1) sm += __shfl_xor_sync(0xffffffffu, sm, off);
    float rs = 1.f / sm;
    float4 o = {e[0] * rs, e[1] * rs, e[2] * rs, e[3] * rs};
    *(float4*)&out[(size_t)i * FEAT + f4] = o;
}

// ---------------- launch ------------------------------------------------------
extern "C" void kernel_launch(void* const* d_in, const int* in_sizes, int n_in,
                              void* d_out, int out_size) {
    const float* x   = (const float*)d_in[0];   // [12288, 512]
    const float* v   = (const float*)d_in[1];   // [128, 512]
    const float* g   = (const float*)d_in[2];   // [128]
    const float* b   = (const float*)d_in[3];   // [128]
    const float* att = (const float*)d_in[4];   // [256]
    float* out = (float*)d_out;                 // [12288, 128]

    const int smem = (2 * 64 * SA + 2 * 128 * SA) * 2;   // 55296 bytes
    cudaFuncSetAttribute(gemm_mma_kernel, cudaFuncAttributeMaxDynamicSharedMemorySize, smem);

    prep_kernel<<<FEAT, 128>>>(v, g);
    gemm_mma_kernel<<<NROW / 64, 256, smem>>>(x, b, att);
    sort_kernel<<<48, 256>>>();
    scanAB_kernel<<<NBR, 256>>>();
    combine_kernel<<<NROW / 4, 128>>>(out);
}

// round 9
// speedup vs baseline: 3.8417x; 1.0324x over previous
#include <cuda_runtime.h>
#include <cuda_bf16.h>
#include <math.h>
#include <stdint.h>

#define NROW 12288
#define DIM  512
#define FEAT 128
#define TR   64            // rows per scan tile
#define NBR  192           // NROW / TR
#define SA   72            // padded bf16 row stride in smem (conflict-free)
#define NBUK 4096
#define ABUF (64 * SA)     // ushorts per A array
#define BBUF (128 * SA)    // ushorts per B array

// ---------------- scratch (device globals; allocations forbidden) -----------
__device__ float g_scale[FEAT];
__device__ unsigned short g_vhi[FEAT * DIM];
__device__ unsigned short g_vlo[FEAT * DIM];
__device__ float g_z[NROW * FEAT];
__device__ float g_s[NROW];
__device__ float g_d[NROW];
__device__ unsigned long long g_dkey[NROW];
__device__ int   g_bin[NROW];
__device__ int   g_hist[NBUK];
__device__ int   g_hcur[NBUK];
__device__ int   g_hstart[NBUK];
__device__ unsigned long long g_bkeys[NROW];
__device__ unsigned int g_kmin, g_kmax;
__device__ int   g_inv[NROW];
__device__ float g_sortedD[NROW];
__device__ float g_expD[NROW];
__device__ float g_S0[(NROW + 1) * FEAT];
__device__ float g_SufE[(NROW + 1) * FEAT];
__device__ float g_c1[NROW + 1];
__device__ float g_T0[NBR * FEAT];
__device__ float g_TS[NBR * FEAT];
__device__ float g_Tc[NBR];
__device__ float g_off0[(NBR + 1) * FEAT];
__device__ float g_offS[(NBR + 1) * FEAT];
__device__ float g_offc[NBR + 1];
__device__ int   g_cnt1, g_gen1;   // sort-kernel barrier
__device__ int   g_cnt2, g_gen2;   // scan-kernel barrier

// ---------------- helpers -----------------------------------------------------
__device__ __forceinline__ void grid_barrier(int expected, int* cnt, int* gen) {
    __syncthreads();
    if (threadIdx.x == 0) {
        int g0 = *((volatile int*)gen);
        __threadfence();
        if (atomicAdd(cnt, 1) == expected - 1) {
            *((volatile int*)cnt) = 0;
            __threadfence();
            atomicAdd(gen, 1);
        } else {
            while (*((volatile int*)gen) == g0) { __nanosleep(64); }
            __threadfence();
        }
    }
    __syncthreads();
}
__device__ __forceinline__ unsigned int float_key(float x) {
    unsigned int u = __float_as_uint(x);
    return (u & 0x80000000u) ? ~u : (u | 0x80000000u);
}
__device__ __forceinline__ uint32_t smem_u32(const void* p) {
    uint32_t a;
    asm("{ .reg .u64 t; cvta.to.shared.u64 t, %1; cvt.u32.u64 %0, t; }" : "=r"(a) : "l"(p));
    return a;
}
__device__ __forceinline__ void mma_bf16(float* c, const uint32_t* a,
                                         uint32_t b0, uint32_t b1) {
    asm volatile(
        "mma.sync.aligned.m16n8k16.row.col.f32.bf16.bf16.f32 "
        "{%0,%1,%2,%3}, {%4,%5,%6,%7}, {%8,%9}, {%0,%1,%2,%3};"
        : "+f"(c[0]), "+f"(c[1]), "+f"(c[2]), "+f"(c[3])
        : "r"(a[0]), "r"(a[1]), "r"(a[2]), "r"(a[3]), "r"(b0), "r"(b1));
}
#define LDSM4(r, addr) \
    asm volatile("ldmatrix.sync.aligned.m8n8.x4.shared.b16 {%0,%1,%2,%3}, [%4];" \
        : "=r"((r)[0]), "=r"((r)[1]), "=r"((r)[2]), "=r"((r)[3]) : "r"(addr))
__device__ __forceinline__ void cp16(uint32_t s, const void* g) {
    asm volatile("cp.async.cg.shared.global [%0], [%1], 16;" :: "r"(s), "l"(g));
}

// ---------------- 1) prep: scale + v split + hist zero + key-range reset -----
__global__ void prep_kernel(const float* __restrict__ v, const float* __restrict__ g) {
    int f = blockIdx.x;
    int t = threadIdx.x;
    int idx = f * 128 + t;
    if (idx < NBUK) g_hist[idx] = 0;
    else if (idx < 2 * NBUK) g_hcur[idx - NBUK] = 0;
    else if (idx == 2 * NBUK) { g_kmin = 0xFFFFFFFFu; g_kmax = 0u; }

    float ss = 0.f;
    for (int q = t; q < DIM; q += 128) {
        float vv = v[(size_t)f * DIM + q];
        ss += vv * vv;
    }
    __shared__ float red[4];
    __shared__ float s_sc;
    for (int off = 16; off; off >>= 1) ss += __shfl_xor_sync(0xffffffffu, ss, off);
    if ((t & 31) == 0) red[t >> 5] = ss;
    __syncthreads();
    if (t == 0) {
        float sc = g[f] / sqrtf(red[0] + red[1] + red[2] + red[3]);
        g_scale[f] = sc;
        s_sc = sc;
    }
    __syncthreads();
    float sc = s_sc;
    for (int k = t; k < DIM; k += 128) {
        float val = v[(size_t)f * DIM + k] * sc;
        __nv_bfloat16 h = __float2bfloat16(val);
        float lo = val - __bfloat162float(h);
        g_vhi[f * DIM + k] = __bfloat16_as_ushort(h);
        g_vlo[f * DIM + k] = __bfloat16_as_ushort(__float2bfloat16(lo));
    }
}

// ---------------- 2) HMMA GEMM: cp.async double-buffered B, prefetched A -----
__global__ void __launch_bounds__(256, 2) gemm_mma_kernel(const float* __restrict__ x,
                                                          const float* __restrict__ b,
                                                          const float* __restrict__ att) {
    extern __shared__ unsigned short sm[];
    unsigned short* aH = sm;                         // 64*SA
    unsigned short* aL = sm + ABUF;
    // B buffers: [bH0 | bL0 | bH1 | bL1]
    unsigned short* bB = sm + 2 * ABUF;
    float* sdp = (float*)sm;                         // reused after mainloop

    const int tid  = threadIdx.x;
    const int w    = tid >> 5;
    const int lane = tid & 31;
    const int g    = lane >> 2;
    const int tig  = lane & 3;
    const int mw   = w & 3;
    const int nw   = w >> 2;
    const int bm   = blockIdx.x * 64;
    const int rb   = mw * 16;
    const int n0   = nw * 64;

    const uint32_t aHs = smem_u32(aH), aLs = smem_u32(aL);
    const uint32_t bBs = smem_u32(bB);
    const uint32_t BOFF = 2 * BBUF * 2;              // bytes per (hi,lo) buffer pair

    const int rA = (lane & 7) + ((lane >> 3) & 1) * 8;
    const int cA = (lane >> 4) * 8;
    const uint32_t aAdH = aHs + ((rb + rA) * SA + cA) * 2;
    const uint32_t aAdL = aLs + ((rb + rA) * SA + cA) * 2;
    const int rB = (lane & 7) + (lane >> 4) * 8;
    const int cB = ((lane >> 3) & 1) * 8;
    uint32_t bAdH[4], bAdL[4];
#pragma unroll
    for (int j = 0; j < 4; j++) {
        bAdH[j] = bBs + ((n0 + j * 16 + rB) * SA + cB) * 2;
        bAdL[j] = bBs + BBUF * 2 + ((n0 + j * 16 + rB) * SA + cB) * 2;
    }

    // B staging coords
    const int brr = tid >> 3;        // row 0..31 step; covers 128 rows in 4 passes
    const int bu  = tid & 7;         // 16B unit

    float acc[8][4];
#pragma unroll
    for (int nt = 0; nt < 8; nt++)
#pragma unroll
        for (int q = 0; q < 4; q++) acc[nt][q] = 0.f;

    // ---- prologue: issue B(0), preload A(0) regs ----
#pragma unroll
    for (int p = 0; p < 4; p++) {
        int r = p * 32 + brr;
        size_t gv = (size_t)r * DIM + bu * 8;
        uint32_t so = (uint32_t)(r * SA + bu * 8) * 2;
        cp16(bBs + so, g_vhi + gv);
        cp16(bBs + BBUF * 2 + so, g_vlo + gv);
    }
    asm volatile("cp.async.commit_group;" ::: "memory");

    float4 xr[4];
#pragma unroll
    for (int p = 0; p < 4; p++) {
        int li = tid + p * 256;
        int r  = li >> 4;
        int c4 = (li & 15) * 4;
        xr[p] = *(const float4*)(x + (size_t)(bm + r) * DIM + c4);
    }

    for (int c = 0; c < 8; c++) {
        const uint32_t boff = (uint32_t)(c & 1) * BOFF;
        // ---- convert & store A(c) from regs ----
#pragma unroll
        for (int p = 0; p < 4; p++) {
            int li = tid + p * 256;
            int r  = li >> 4;
            int c4 = (li & 15) * 4;
            float4 xv = xr[p];
            __nv_bfloat16 h0 = __float2bfloat16(xv.x);
            __nv_bfloat16 h1 = __float2bfloat16(xv.y);
            __nv_bfloat16 h2 = __float2bfloat16(xv.z);
            __nv_bfloat16 h3 = __float2bfloat16(xv.w);
            uint2 hv, lv;
            hv.x = ((uint32_t)__bfloat16_as_ushort(h1) << 16) | __bfloat16_as_ushort(h0);
            hv.y = ((uint32_t)__bfloat16_as_ushort(h3) << 16) | __bfloat16_as_ushort(h2);
            __nv_bfloat16 l0 = __float2bfloat16(xv.x - __bfloat162float(h0));
            __nv_bfloat16 l1 = __float2bfloat16(xv.y - __bfloat162float(h1));
            __nv_bfloat16 l2 = __float2bfloat16(xv.z - __bfloat162float(h2));
            __nv_bfloat16 l3 = __float2bfloat16(xv.w - __bfloat162float(h3));
            lv.x = ((uint32_t)__bfloat16_as_ushort(l1) << 16) | __bfloat16_as_ushort(l0);
            lv.y = ((uint32_t)__bfloat16_as_ushort(l3) << 16) | __bfloat16_as_ushort(l2);
            *(uint2*)&aH[r * SA + c4] = hv;
            *(uint2*)&aL[r * SA + c4] = lv;
        }
        // ---- issue B(c+1) into other buffer ----
        if (c < 7) {
            const int k0n = (c + 1) * 64;
            const uint32_t bo2 = (uint32_t)((c + 1) & 1) * BOFF;
#pragma unroll
            for (int p = 0; p < 4; p++) {
                int r = p * 32 + brr;
                size_t gv = (size_t)r * DIM + k0n + bu * 8;
                uint32_t so = (uint32_t)(r * SA + bu * 8) * 2;
                cp16(bBs + bo2 + so, g_vhi + gv);
                cp16(bBs + bo2 + BBUF * 2 + so, g_vlo + gv);
            }
            asm volatile("cp.async.commit_group;" ::: "memory");
            asm volatile("cp.async.wait_group 1;" ::: "memory");
        } else {
            asm volatile("cp.async.wait_group 0;" ::: "memory");
        }
        __syncthreads();

        // ---- prefetch A(c+1) regs (overlaps with MMA below) ----
        if (c < 7) {
            const int k0n = (c + 1) * 64;
#pragma unroll
            for (int p = 0; p < 4; p++) {
                int li = tid + p * 256;
                int r  = li >> 4;
                int c4 = (li & 15) * 4;
                xr[p] = *(const float4*)(x + (size_t)(bm + r) * DIM + k0n + c4);
            }
        }

        // ---- MMA over buffer (c&1) ----
#pragma unroll
        for (int kt = 0; kt < 4; kt++) {
            uint32_t ah[4], al[4];
            LDSM4(ah, aAdH + kt * 32);
            LDSM4(al, aAdL + kt * 32);
#pragma unroll
            for (int j = 0; j < 4; j++) {
                uint32_t bh[4], bl[4];
                LDSM4(bh, bAdH[j] + boff + kt * 32);
                LDSM4(bl, bAdL[j] + boff + kt * 32);
                mma_bf16(acc[2 * j],     ah, bh[0], bh[1]);
                mma_bf16(acc[2 * j],     ah, bl[0], bl[1]);
                mma_bf16(acc[2 * j],     al, bh[0], bh[1]);
                mma_bf16(acc[2 * j + 1], ah, bh[2], bh[3]);
                mma_bf16(acc[2 * j + 1], ah, bl[2], bl[3]);
                mma_bf16(acc[2 * j + 1], al, bh[2], bh[3]);
            }
        }
        __syncthreads();
    }

    // ---- epilogue ----
    float sv[2] = {0.f, 0.f}, dv[2] = {0.f, 0.f};
    const int row0 = bm + rb + g;
#pragma unroll
    for (int nt = 0; nt < 8; nt++) {
        int cb = n0 + nt * 8 + tig * 2;
        float2 bb = *(const float2*)&b[cb];
        float2 as = *(const float2*)&att[cb];
        float2 ad = *(const float2*)&att[FEAT + cb];
        float z0 = acc[nt][0] + bb.x;
        float z1 = acc[nt][1] + bb.y;
        float z2 = acc[nt][2] + bb.x;
        float z3 = acc[nt][3] + bb.y;
        *(float2*)&g_z[(size_t)row0 * FEAT + cb]       = make_float2(z0, z1);
        *(float2*)&g_z[(size_t)(row0 + 8) * FEAT + cb] = make_float2(z2, z3);
        sv[0] += z0 * as.x + z1 * as.y;
        sv[1] += z2 * as.x + z3 * as.y;
        dv[0] += z0 * ad.x + z1 * ad.y;
        dv[1] += z2 * ad.x + z3 * ad.y;
    }
#pragma unroll
    for (int h = 0; h < 2; h++) {
        sv[h] += __shfl_xor_sync(0xffffffffu, sv[h], 1);
        sv[h] += __shfl_xor_sync(0xffffffffu, sv[h], 2);
        dv[h] += __shfl_xor_sync(0xffffffffu, dv[h], 1);
        dv[h] += __shfl_xor_sync(0xffffffffu, dv[h], 2);
    }
    if (tig == 0) {
        int rl0 = rb + g;
        sdp[(nw * 64 + rl0) * 2 + 0]     = sv[0];
        sdp[(nw * 64 + rl0) * 2 + 1]     = dv[0];
        sdp[(nw * 64 + rl0 + 8) * 2 + 0] = sv[1];
        sdp[(nw * 64 + rl0 + 8) * 2 + 1] = dv[1];
    }
    __syncthreads();
    if (tid < 64) {
        float s = sdp[tid * 2]     + sdp[(64 + tid) * 2];
        float d = sdp[tid * 2 + 1] + sdp[(64 + tid) * 2 + 1];
        int row = bm + tid;
        g_s[row] = s;
        g_d[row] = d;
        unsigned int key = float_key(d);
        g_dkey[row] = ((unsigned long long)key << 32) | (unsigned int)row;
        unsigned int kmn = key, kmx = key;
#pragma unroll
        for (int off = 16; off; off >>= 1) {
            kmn = min(kmn, __shfl_xor_sync(0xffffffffu, kmn, off));
            kmx = max(kmx, __shfl_xor_sync(0xffffffffu, kmx, off));
        }
        if (lane == 0) {
            atomicMin(&g_kmin, kmn);
            atomicMax(&g_kmax, kmx);
        }
    }
}

// ---------------- 3) fused sort: hist -> scan -> place -> rank ---------------
__global__ void __launch_bounds__(256) sort_kernel() {
    const int nb  = 48;
    const int tid = threadIdx.x;
    const int bid = blockIdx.x;
    const int i   = bid * 256 + tid;

    unsigned long long kj = g_dkey[i];
    unsigned int key  = (unsigned int)(kj >> 32);
    unsigned int kmin = g_kmin;
    unsigned long long range = (unsigned long long)(g_kmax - kmin) + 1ull;
    int bin = (int)(((unsigned long long)(key - kmin) * NBUK) / range);
    g_bin[i] = bin;
    atomicAdd(&g_hist[bin], 1);
    grid_barrier(nb, &g_cnt1, &g_gen1);

    if (bid == 0) {
        __shared__ int ws[8];
        int base = tid * 16;
        int loc[16];
        int s = 0;
#pragma unroll
        for (int q = 0; q < 16; q++) { loc[q] = g_hist[base + q]; s += loc[q]; }
        int lane = tid & 31, wid = tid >> 5;
        int sc = s;
#pragma unroll
        for (int off = 1; off < 32; off <<= 1) {
            int o = __shfl_up_sync(0xffffffffu, sc, off);
            if (lane >= off) sc += o;
        }
        if (lane == 31) ws[wid] = sc;
        __syncthreads();
        if (tid == 0) {
            int run = 0;
#pragma unroll
            for (int q = 0; q < 8; q++) { int t2 = ws[q]; ws[q] = run; run += t2; }
        }
        __syncthreads();
        int run = ws[wid] + sc - s;
#pragma unroll
        for (int q = 0; q < 16; q++) { g_hstart[base + q] = run; run += loc[q]; }
    }
    grid_barrier(nb, &g_cnt1, &g_gen1);

    int pos = atomicAdd(&g_hcur[bin], 1);
    g_bkeys[g_hstart[bin] + pos] = kj;
    grid_barrier(nb, &g_cnt1, &g_gen1);

    int st  = g_hstart[bin];
    int cnt = g_hist[bin];
    int c = 0;
    for (int q = 0; q < cnt; q++) c += (g_bkeys[st + q] < kj) ? 1 : 0;
    int r = st + c;
    float d = g_d[i];
    g_inv[r]     = i;
    g_sortedD[r] = d;
    g_expD[r]    = expf(d);
}

// ---------------- 4) fused scans: MLP-batched local + parallel totals --------
__global__ void __launch_bounds__(256) scanAB_kernel() {
    int b    = blockIdx.x;
    int tid  = threadIdx.x;
    int base = b * TR;
    __shared__ int   jidx[TR];
    __shared__ float ed[TR];
    if (tid < TR) {
        jidx[tid] = g_inv[base + tid];
        ed[tid]   = g_expD[base + tid];
    }
    __syncthreads();

    if (tid < 128) {
        int f = tid;
        float acc = 0.f;
#pragma unroll
        for (int bt = 0; bt < 4; bt++) {
            float vals[16];
#pragma unroll
            for (int q = 0; q < 16; q++)
                vals[q] = g_z[(size_t)jidx[bt * 16 + q] * FEAT + f];
#pragma unroll
            for (int q = 0; q < 16; q++) {
                g_S0[(size_t)(base + bt * 16 + q) * FEAT + f] = acc;
                acc += vals[q];
            }
        }
        g_T0[b * FEAT + f] = acc;

        if (f < 32) {
            float v0 = ed[2 * f], v1 = ed[2 * f + 1];
            float seg = v0 + v1;
            float suf = seg;
#pragma unroll
            for (int off = 1; off < 32; off <<= 1) {
                float t2 = __shfl_down_sync(0xffffffffu, suf, off);
                if (f + off < 32) suf += t2;
            }
            float excl = suf - seg;
            g_c1[base + 2 * f + 1] = excl + v1;
            g_c1[base + 2 * f]     = excl + v1 + v0;
            if (f == 0) g_Tc[b] = suf;
        }
    } else {
        int f = tid - 128;
        float accS = 0.f;
#pragma unroll
        for (int bt = 3; bt >= 0; bt--) {
            float vals[16];
#pragma unroll
            for (int q = 0; q < 16; q++)
                vals[q] = ed[bt * 16 + q] * g_z[(size_t)jidx[bt * 16 + q] * FEAT + f];
#pragma unroll
            for (int q = 15; q >= 0; q--) {
                accS += vals[q];
                g_SufE[(size_t)(base + bt * 16 + q) * FEAT + f] = accS;
            }
        }
        g_TS[b * FEAT + f] = accS;
    }

    grid_barrier(NBR, &g_cnt2, &g_gen2);

    if (b < 128) {
        int f = b;
        bool act = tid < NBR;
        float v0 = act ? g_T0[tid * FEAT + f] : 0.f;
        float vS = act ? g_TS[tid * FEAT + f] : 0.f;
        float i0 = v0, iS = vS;
        int lane = tid & 31, wid = tid >> 5;
#pragma unroll
        for (int off = 1; off < 32; off <<= 1) {
            float a0 = __shfl_up_sync(0xffffffffu, i0, off);
            float aS = __shfl_up_sync(0xffffffffu, iS, off);
            if (lane >= off) { i0 += a0; iS += aS; }
        }
        __shared__ float w0[8], wS[8];
        __shared__ float tot0s, totSs;
        if (lane == 31) { w0[wid] = i0; wS[wid] = iS; }
        __syncthreads();
        if (tid == 0) {
            float r0 = 0.f, rS = 0.f;
#pragma unroll
            for (int q = 0; q < 8; q++) {
                float t0 = w0[q], tS = wS[q];
                w0[q] = r0; wS[q] = rS;
                r0 += t0; rS += tS;
            }
            tot0s = r0; totSs = rS;
        }
        __syncthreads();
        i0 += w0[wid];
        iS += wS[wid];
        if (act) {
            g_off0[tid * FEAT + f] = i0 - v0;
            g_offS[tid * FEAT + f] = totSs - iS;
        }
        if (tid == 0) {
            g_off0[NBR * FEAT + f] = tot0s;
            g_offS[NBR * FEAT + f] = 0.f;
            g_S0[(size_t)NROW * FEAT + f]   = 0.f;
            g_SufE[(size_t)NROW * FEAT + f] = 0.f;
        }
    } else if (b == 128) {
        bool act = tid < NBR;
        float vc = act ? g_Tc[tid] : 0.f;
        float ic = vc;
        int lane = tid & 31, wid = tid >> 5;
#pragma unroll
        for (int off = 1; off < 32; off <<= 1) {
            float a = __shfl_up_sync(0xffffffffu, ic, off);
            if (lane >= off) ic += a;
        }
        __shared__ float wc[8];
        __shared__ float totc;
        if (lane == 31) wc[wid] = ic;
        __syncthreads();
        if (tid == 0) {
            float r = 0.f;
#pragma unroll
            for (int q = 0; q < 8; q++) { float t2 = wc[q]; wc[q] = r; r += t2; }
            totc = r;
        }
        __syncthreads();
        ic += wc[wid];
        if (act) g_offc[tid] = totc - ic;
        if (tid == 0) { g_offc[NBR] = 0.f; g_c1[NROW] = 0.f; }
    }
}

// ---------------- 5) combine: warp per row, shuffle-only softmax -------------
__global__ void __launch_bounds__(128) combine_kernel(float* __restrict__ out) {
    int w    = threadIdx.x >> 5;
    int lane = threadIdx.x & 31;
    int i    = blockIdx.x * 4 + w;
    int f4   = lane * 4;

    float s = g_s[i];
    float thr = -s;
    int lo = 0, hi = NROW;
#pragma unroll 1
    while (lo < hi) {
        int mid = (lo + hi) >> 1;
        if (g_sortedD[mid] <= thr) lo = mid + 1;
        else hi = mid;
    }
    int k   = lo;
    int blk = k >> 6;

    float dmax  = g_sortedD[NROW - 1];
    float m     = fmaxf(0.f, s + dmax);
    float alpha = expf(s - m);
    float beta  = expf(-m);
    float den   = alpha * (g_offc[blk] + g_c1[k]) + beta * (float)k;
    float rden  = 1.f / den;

    float4 SufE = *(const float4*)&g_SufE[(size_t)k * FEAT + f4];
    float4 S0   = *(const float4*)&g_S0[(size_t)k * FEAT + f4];
    float4 offS = *(const float4*)&g_offS[(size_t)blk * FEAT + f4];
    float4 off0 = *(const float4*)&g_off0[(size_t)blk * FEAT + f4];
    float4 zv   = *(const float4*)&g_z[(size_t)i * FEAT + f4];

    float z2[4];
    z2[0] = (alpha * (offS.x + SufE.x) + beta * (off0.x + S0.x)) * rden + zv.x;
    z2[1] = (alpha * (offS.y + SufE.y) + beta * (off0.y + S0.y)) * rden + zv.y;
    z2[2] = (alpha * (offS.z + SufE.z) + beta * (off0.z + S0.z)) * rden + zv.z;
    z2[3] = (alpha * (offS.w + SufE.w) + beta * (off0.w + S0.w)) * rden + zv.w;

    float mx = fmaxf(fmaxf(z2[0], z2[1]), fmaxf(z2[2], z2[3]));
#pragma unroll
    for (int off = 16; off; off >>= 1) mx = fmaxf(mx, __shfl_xor_sync(0xffffffffu, mx, off));
    float e[4];
    float sm = 0.f;
#pragma unroll
    for (int q = 0; q < 4; q++) { e[q] = expf(z2[q] - mx); sm += e[q]; }
#pragma unroll
    for (int off = 16; off; off >>= 1) sm += __shfl_xor_sync(0xffffffffu, sm, off);
    float rs = 1.f / sm;
    float4 o = {e[0] * rs, e[1] * rs, e[2] * rs, e[3] * rs};
    *(float4*)&out[(size_t)i * FEAT + f4] = o;
}

// ---------------- launch ------------------------------------------------------
extern "C" void kernel_launch(void* const* d_in, const int* in_sizes, int n_in,
                              void* d_out, int out_size) {
    const float* x   = (const float*)d_in[0];   // [12288, 512]
    const float* v   = (const float*)d_in[1];   // [128, 512]
    const float* g   = (const float*)d_in[2];   // [128]
    const float* b   = (const float*)d_in[3];   // [128]
    const float* att = (const float*)d_in[4];   // [256]
    float* out = (float*)d_out;                 // [12288, 128]

    const int smem = (2 * ABUF + 4 * BBUF) * 2;   // 92160 bytes
    cudaFuncSetAttribute(gemm_mma_kernel, cudaFuncAttributeMaxDynamicSharedMemorySize, smem);

    prep_kernel<<<FEAT, 128>>>(v, g);
    gemm_mma_kernel<<<NROW / 64, 256, smem>>>(x, b, att);
    sort_kernel<<<48, 256>>>();
    scanAB_kernel<<<NBR, 256>>>();
    combine_kernel<<<NROW / 4, 128>>>(out);
}